// round 1
// baseline (speedup 1.0000x reference)
#include <cuda_runtime.h>

#define HDIM 768
#define NGRAPH 256
#define C3H (3 * HDIM)

// Scratch (allocation-free rule: __device__ globals)
__device__ float g_pooled[NGRAPH * C3H];   // [B, 3H]: nodes | edges | lang
__device__ float g_mid[NGRAPH * HDIM];
__device__ float g_mid2[NGRAPH * HDIM];

__global__ void zero_pooled_kernel() {
    int i = blockIdx.x * blockDim.x + threadIdx.x;
    if (i < NGRAPH * C3H) g_pooled[i] = 0.f;
}

// ---------------------------------------------------------------------------
// Segment sum: sorted segment ids. Each block owns SEG_ROWS contiguous rows,
// 192 threads, one float4 (16B) per thread per row (192*16 = 3072B = full row).
// Register accumulation while seg unchanged; atomicAdd flush on change.
// Unroll x4 rows for MLP=4 on the fast path (all same segment).
// ---------------------------------------------------------------------------
#define SEG_ROWS 512

__global__ void seg_sum_kernel(const float* __restrict__ feat,
                               const int* __restrict__ seg,
                               int n, int col_off) {
    const int tid = threadIdx.x;  // 0..191
    long r0 = (long)blockIdx.x * SEG_ROWS;
    long r1 = r0 + SEG_ROWS;
    if (r1 > n) r1 = n;
    if (r0 >= r1) return;

    const float* base = feat + tid * 4;
    float4 acc = make_float4(0.f, 0.f, 0.f, 0.f);
    int cur = __ldg(seg + r0);

    long r = r0;
    while (r + 4 <= r1) {
        int s3 = __ldg(seg + r + 3);
        float4 v0 = *reinterpret_cast<const float4*>(base + (r + 0) * HDIM);
        float4 v1 = *reinterpret_cast<const float4*>(base + (r + 1) * HDIM);
        float4 v2 = *reinterpret_cast<const float4*>(base + (r + 2) * HDIM);
        float4 v3 = *reinterpret_cast<const float4*>(base + (r + 3) * HDIM);
        if (s3 == cur) {
            // sorted => seg[r..r+3] all == cur
            acc.x += v0.x + v1.x + v2.x + v3.x;
            acc.y += v0.y + v1.y + v2.y + v3.y;
            acc.z += v0.z + v1.z + v2.z + v3.z;
            acc.w += v0.w + v1.w + v2.w + v3.w;
        } else {
            int s0 = __ldg(seg + r);
            int s1 = __ldg(seg + r + 1);
            int s2 = __ldg(seg + r + 2);
            float4 vs[4] = {v0, v1, v2, v3};
            int ss[4] = {s0, s1, s2, s3};
            #pragma unroll
            for (int q = 0; q < 4; q++) {
                if (ss[q] != cur) {
                    float* o = g_pooled + (long)cur * C3H + col_off + tid * 4;
                    atomicAdd(o + 0, acc.x);
                    atomicAdd(o + 1, acc.y);
                    atomicAdd(o + 2, acc.z);
                    atomicAdd(o + 3, acc.w);
                    acc = make_float4(0.f, 0.f, 0.f, 0.f);
                    cur = ss[q];
                }
                acc.x += vs[q].x; acc.y += vs[q].y;
                acc.z += vs[q].z; acc.w += vs[q].w;
            }
        }
        r += 4;
    }
    for (; r < r1; ++r) {
        int s = __ldg(seg + r);
        if (s != cur) {
            float* o = g_pooled + (long)cur * C3H + col_off + tid * 4;
            atomicAdd(o + 0, acc.x);
            atomicAdd(o + 1, acc.y);
            atomicAdd(o + 2, acc.z);
            atomicAdd(o + 3, acc.w);
            acc = make_float4(0.f, 0.f, 0.f, 0.f);
            cur = s;
        }
        float4 v = *reinterpret_cast<const float4*>(base + r * HDIM);
        acc.x += v.x; acc.y += v.y; acc.z += v.z; acc.w += v.w;
    }
    {
        float* o = g_pooled + (long)cur * C3H + col_off + tid * 4;
        atomicAdd(o + 0, acc.x);
        atomicAdd(o + 1, acc.y);
        atomicAdd(o + 2, acc.z);
        atomicAdd(o + 3, acc.w);
    }
}

// ---------------------------------------------------------------------------
// GEMM: C[M,N] = A[M,K] @ W[K,N] + bias, optional relu.
// A row-major (lda), W row-major (ldw), C row-major (ldc).
// BM=32, BN=64, BK=32, TM=2, TN=4, 256 threads.
// Requires M % 32 == 0 and K % 32 == 0 (true here: M=256, K in {768, 2304}).
// N may be ragged (3129): W loads scalar + guarded, stores guarded.
// ---------------------------------------------------------------------------
template <bool RELU>
__global__ void gemm_bias_kernel(const float* __restrict__ A, int lda,
                                 const float* __restrict__ W, int ldw,
                                 const float* __restrict__ bias,
                                 float* __restrict__ C, int ldc,
                                 int N, int K) {
    constexpr int BM = 32, BN = 64, BK = 32, TM = 2, TN = 4;
    __shared__ float As[BK][BM + 1];  // +1 pad: conflict-free transposed store
    __shared__ float Ws[BK][BN];

    const int t = threadIdx.x;            // 0..255
    const int bm = blockIdx.y * BM;
    const int bn = blockIdx.x * BN;
    const int tx = t & 15;                // 16 -> 64 cols
    const int ty = t >> 4;                // 16 -> 32 rows
    const int a_row = t >> 3;             // 0..31
    const int a_col = (t & 7) * 4;        // 0..28

    float acc[TM][TN] = {};

    for (int k0 = 0; k0 < K; k0 += BK) {
        // A tile (float4, aligned: lda multiple of 4, k0 mult 32, a_col mult 4)
        float4 av = *reinterpret_cast<const float4*>(
            A + (long)(bm + a_row) * lda + k0 + a_col);
        As[a_col + 0][a_row] = av.x;
        As[a_col + 1][a_row] = av.y;
        As[a_col + 2][a_row] = av.z;
        As[a_col + 3][a_row] = av.w;

        // W tile: 32x64 scalar loads, coalesced (64 consecutive n per row)
        #pragma unroll
        for (int i = 0; i < 8; i++) {
            int idx = t + i * 256;
            int wr = idx >> 6;
            int wc = idx & 63;
            int gn = bn + wc;
            Ws[wr][wc] = (gn < N) ? __ldg(W + (long)(k0 + wr) * ldw + gn) : 0.f;
        }
        __syncthreads();

        #pragma unroll
        for (int kk = 0; kk < BK; kk++) {
            float a0 = As[kk][ty * TM + 0];
            float a1 = As[kk][ty * TM + 1];
            float4 b = *reinterpret_cast<const float4*>(&Ws[kk][tx * TN]);
            acc[0][0] += a0 * b.x; acc[0][1] += a0 * b.y;
            acc[0][2] += a0 * b.z; acc[0][3] += a0 * b.w;
            acc[1][0] += a1 * b.x; acc[1][1] += a1 * b.y;
            acc[1][2] += a1 * b.z; acc[1][3] += a1 * b.w;
        }
        __syncthreads();
    }

    #pragma unroll
    for (int i = 0; i < TM; i++) {
        int gm = bm + ty * TM + i;
        #pragma unroll
        for (int j = 0; j < TN; j++) {
            int gn = bn + tx * TN + j;
            if (gn < N) {
                float c = acc[i][j] + __ldg(bias + gn);
                if (RELU) c = fmaxf(c, 0.f);
                C[(long)gm * ldc + gn] = c;
            }
        }
    }
}

extern "C" void kernel_launch(void* const* d_in, const int* in_sizes, int n_in,
                              void* d_out, int out_size) {
    const float* node_feat = (const float*)d_in[0];
    const float* edge_feat = (const float*)d_in[1];
    const float* qemb      = (const float*)d_in[2];
    const int*   node_seg  = (const int*)d_in[3];
    const int*   edge_seg  = (const int*)d_in[4];
    const float* W_lang = (const float*)d_in[5];
    const float* b_lang = (const float*)d_in[6];
    const float* W_mid  = (const float*)d_in[7];
    const float* b_mid  = (const float*)d_in[8];
    const float* W_mid2 = (const float*)d_in[9];
    const float* b_mid2 = (const float*)d_in[10];
    const float* W_ans  = (const float*)d_in[11];
    const float* b_ans  = (const float*)d_in[12];

    const int N = in_sizes[3];   // num nodes
    const int E = in_sizes[4];   // num edges
    const int A = in_sizes[12];  // answer dim (3129)

    float *pooled, *mid, *mid2;
    cudaGetSymbolAddress((void**)&pooled, g_pooled);
    cudaGetSymbolAddress((void**)&mid, g_mid);
    cudaGetSymbolAddress((void**)&mid2, g_mid2);

    zero_pooled_kernel<<<(NGRAPH * C3H + 255) / 256, 256>>>();

    seg_sum_kernel<<<(N + SEG_ROWS - 1) / SEG_ROWS, 192>>>(node_feat, node_seg, N, 0);
    seg_sum_kernel<<<(E + SEG_ROWS - 1) / SEG_ROWS, 192>>>(edge_feat, edge_seg, E, HDIM);

    // lang = qemb @ W_lang + b_lang  -> pooled[:, 2H:3H]
    gemm_bias_kernel<false><<<dim3((HDIM + 63) / 64, NGRAPH / 32), 256>>>(
        qemb, HDIM, W_lang, HDIM, b_lang, pooled + 2 * HDIM, C3H, HDIM, HDIM);

    // mid = relu(pooled @ W_mid + b_mid)   [256,2304] x [2304,768]
    gemm_bias_kernel<true><<<dim3((HDIM + 63) / 64, NGRAPH / 32), 256>>>(
        pooled, C3H, W_mid, HDIM, b_mid, mid, HDIM, HDIM, C3H);

    // mid2 = relu(mid @ W_mid2 + b_mid2)   [256,768] x [768,768]
    gemm_bias_kernel<true><<<dim3((HDIM + 63) / 64, NGRAPH / 32), 256>>>(
        mid, HDIM, W_mid2, HDIM, b_mid2, mid2, HDIM, HDIM, HDIM);

    // pred = mid2 @ W_ans + b_ans          [256,768] x [768,3129]
    gemm_bias_kernel<false><<<dim3((A + 63) / 64, NGRAPH / 32), 256>>>(
        mid2, HDIM, W_ans, A, b_ans, (float*)d_out, A, A, HDIM);
}

// round 3
// speedup vs baseline: 1.2355x; 1.2355x over previous
#include <cuda_runtime.h>
#include <cstdint>

#define HDIM 768
#define NGRAPH 256
#define C3H (3 * HDIM)

// Scratch (allocation-free rule: __device__ globals)
__device__ float g_pooled[NGRAPH * C3H];   // [B, 3H]: nodes | edges | lang
__device__ float g_mid[NGRAPH * HDIM];
__device__ float g_mid2[NGRAPH * HDIM];
__device__ float g_part[1605632];          // split-K partials (max: 2*256*3129)

__global__ void zero_pooled_kernel() {
    int i = blockIdx.x * blockDim.x + threadIdx.x;
    if (i < NGRAPH * C3H) g_pooled[i] = 0.f;
}

// ---------------------------------------------------------------------------
// Segment sum (unchanged: ~HBM roofline already)
// ---------------------------------------------------------------------------
#define SEG_ROWS 512

__global__ void seg_sum_kernel(const float* __restrict__ feat,
                               const int* __restrict__ seg,
                               int n, int col_off) {
    const int tid = threadIdx.x;  // 0..191
    long r0 = (long)blockIdx.x * SEG_ROWS;
    long r1 = r0 + SEG_ROWS;
    if (r1 > n) r1 = n;
    if (r0 >= r1) return;

    const float* base = feat + tid * 4;
    float4 acc = make_float4(0.f, 0.f, 0.f, 0.f);
    int cur = __ldg(seg + r0);

    long r = r0;
    while (r + 4 <= r1) {
        int s3 = __ldg(seg + r + 3);
        float4 v0 = *reinterpret_cast<const float4*>(base + (r + 0) * HDIM);
        float4 v1 = *reinterpret_cast<const float4*>(base + (r + 1) * HDIM);
        float4 v2 = *reinterpret_cast<const float4*>(base + (r + 2) * HDIM);
        float4 v3 = *reinterpret_cast<const float4*>(base + (r + 3) * HDIM);
        if (s3 == cur) {
            acc.x += v0.x + v1.x + v2.x + v3.x;
            acc.y += v0.y + v1.y + v2.y + v3.y;
            acc.z += v0.z + v1.z + v2.z + v3.z;
            acc.w += v0.w + v1.w + v2.w + v3.w;
        } else {
            int s0 = __ldg(seg + r);
            int s1 = __ldg(seg + r + 1);
            int s2 = __ldg(seg + r + 2);
            float4 vs[4] = {v0, v1, v2, v3};
            int ss[4] = {s0, s1, s2, s3};
            #pragma unroll
            for (int q = 0; q < 4; q++) {
                if (ss[q] != cur) {
                    float* o = g_pooled + (long)cur * C3H + col_off + tid * 4;
                    atomicAdd(o + 0, acc.x);
                    atomicAdd(o + 1, acc.y);
                    atomicAdd(o + 2, acc.z);
                    atomicAdd(o + 3, acc.w);
                    acc = make_float4(0.f, 0.f, 0.f, 0.f);
                    cur = ss[q];
                }
                acc.x += vs[q].x; acc.y += vs[q].y;
                acc.z += vs[q].z; acc.w += vs[q].w;
            }
        }
        r += 4;
    }
    for (; r < r1; ++r) {
        int s = __ldg(seg + r);
        if (s != cur) {
            float* o = g_pooled + (long)cur * C3H + col_off + tid * 4;
            atomicAdd(o + 0, acc.x);
            atomicAdd(o + 1, acc.y);
            atomicAdd(o + 2, acc.z);
            atomicAdd(o + 3, acc.w);
            acc = make_float4(0.f, 0.f, 0.f, 0.f);
            cur = s;
        }
        float4 v = *reinterpret_cast<const float4*>(base + r * HDIM);
        acc.x += v.x; acc.y += v.y; acc.z += v.z; acc.w += v.w;
    }
    {
        float* o = g_pooled + (long)cur * C3H + col_off + tid * 4;
        atomicAdd(o + 0, acc.x);
        atomicAdd(o + 1, acc.y);
        atomicAdd(o + 2, acc.z);
        atomicAdd(o + 3, acc.w);
    }
}

// ---------------------------------------------------------------------------
// TF32 tensor-core GEMM with 3xTF32 decomposition + split-K.
// BM=64, BN=64, BK=16; 128 threads = 4 warps (2x2), warp tile 32x32.
// ---------------------------------------------------------------------------
__device__ __forceinline__ void tf32split(float x, unsigned& hi, unsigned& lo) {
    unsigned h;
    asm("cvt.rna.tf32.f32 %0, %1;" : "=r"(h) : "f"(x));
    float hf = __uint_as_float(h);
    unsigned l;
    float d = x - hf;
    asm("cvt.rna.tf32.f32 %0, %1;" : "=r"(l) : "f"(d));
    hi = h; lo = l;
}

__device__ __forceinline__ void mma8(float* d, const unsigned* a, const unsigned* b) {
    asm("mma.sync.aligned.m16n8k8.row.col.f32.tf32.tf32.f32 "
        "{%0,%1,%2,%3},{%4,%5,%6,%7},{%8,%9},{%0,%1,%2,%3};"
        : "+f"(d[0]), "+f"(d[1]), "+f"(d[2]), "+f"(d[3])
        : "r"(a[0]), "r"(a[1]), "r"(a[2]), "r"(a[3]), "r"(b[0]), "r"(b[1]));
}

__global__ __launch_bounds__(128) void gemm_tf32_splitk(
    const float* __restrict__ A, int lda,
    const float* __restrict__ W, int ldw,
    float* __restrict__ part,
    int M, int N, int Ksplit) {
    __shared__ float As[64][17];
    __shared__ float Bs[16][66];

    const int t = threadIdx.x;          // 0..127
    const int wid = t >> 5;
    const int lane = t & 31;
    const int wm = (wid & 1) * 32;
    const int wn = (wid >> 1) * 32;
    const int bm = blockIdx.y * 64;
    const int bn = blockIdx.x * 64;
    const int g = lane >> 2;            // 0..7
    const int tq = lane & 3;            // 0..3

    const int kbeg = blockIdx.z * Ksplit;
    const int kend = kbeg + Ksplit;

    const int ar = t >> 1;              // 0..63
    const int ac = (t & 1) * 8;         // 0 or 8

    float acc[2][4][4] = {};

    for (int k0 = kbeg; k0 < kend; k0 += 16) {
        float4 a4a = *reinterpret_cast<const float4*>(A + (long)(bm + ar) * lda + k0 + ac);
        float4 a4b = *reinterpret_cast<const float4*>(A + (long)(bm + ar) * lda + k0 + ac + 4);
        float bv[8];
        #pragma unroll
        for (int i = 0; i < 8; i++) {
            int idx = t + i * 128;      // over 16x64
            int br = idx >> 6;
            int bc = idx & 63;
            int gn = bn + bc;
            bv[i] = (gn < N) ? __ldg(W + (long)(k0 + br) * ldw + gn) : 0.f;
        }
        __syncthreads();
        As[ar][ac + 0] = a4a.x; As[ar][ac + 1] = a4a.y;
        As[ar][ac + 2] = a4a.z; As[ar][ac + 3] = a4a.w;
        As[ar][ac + 4] = a4b.x; As[ar][ac + 5] = a4b.y;
        As[ar][ac + 6] = a4b.z; As[ar][ac + 7] = a4b.w;
        #pragma unroll
        for (int i = 0; i < 8; i++) {
            int idx = t + i * 128;
            Bs[idx >> 6][idx & 63] = bv[i];
        }
        __syncthreads();

        #pragma unroll
        for (int kk = 0; kk < 16; kk += 8) {
            unsigned ah[2][4], al[2][4];
            #pragma unroll
            for (int mt = 0; mt < 2; mt++) {
                int row = wm + mt * 16 + g;
                tf32split(As[row][kk + tq],     ah[mt][0], al[mt][0]);
                tf32split(As[row + 8][kk + tq], ah[mt][1], al[mt][1]);
                tf32split(As[row][kk + tq + 4],     ah[mt][2], al[mt][2]);
                tf32split(As[row + 8][kk + tq + 4], ah[mt][3], al[mt][3]);
            }
            unsigned bh[4][2], bl[4][2];
            #pragma unroll
            for (int nt = 0; nt < 4; nt++) {
                int col = wn + nt * 8 + g;
                tf32split(Bs[kk + tq][col],     bh[nt][0], bl[nt][0]);
                tf32split(Bs[kk + tq + 4][col], bh[nt][1], bl[nt][1]);
            }
            #pragma unroll
            for (int mt = 0; mt < 2; mt++) {
                #pragma unroll
                for (int nt = 0; nt < 4; nt++) {
                    mma8(acc[mt][nt], ah[mt], bl[nt]);   // hi*lo
                    mma8(acc[mt][nt], al[mt], bh[nt]);   // lo*hi
                    mma8(acc[mt][nt], ah[mt], bh[nt]);   // hi*hi
                }
            }
        }
    }

    const long sbase = (long)blockIdx.z * M;
    #pragma unroll
    for (int mt = 0; mt < 2; mt++) {
        int row = bm + wm + mt * 16 + g;
        #pragma unroll
        for (int nt = 0; nt < 4; nt++) {
            int col = bn + wn + nt * 8 + tq * 2;
            float* p0 = part + (sbase + row) * N + col;
            float* p1 = part + (sbase + row + 8) * N + col;
            if (col < N)     { p0[0] = acc[mt][nt][0]; p1[0] = acc[mt][nt][2]; }
            if (col + 1 < N) { p0[1] = acc[mt][nt][1]; p1[1] = acc[mt][nt][3]; }
        }
    }
}

// Reduce split-K partials + bias (+relu), write to out with row stride ldc.
__global__ void reduce_bias_kernel(const float* __restrict__ part,
                                   const float* __restrict__ bias,
                                   float* __restrict__ out, int ldc,
                                   int M, int N, int splits, int relu) {
    int i = blockIdx.x * blockDim.x + threadIdx.x;
    if (i >= M * N) return;
    int m = i / N, n = i - m * N;
    float s = __ldg(bias + n);
    for (int q = 0; q < splits; q++)
        s += part[((long)q * M + m) * N + n];
    if (relu) s = fmaxf(s, 0.f);
    out[(long)m * ldc + n] = s;
}

// ---------------------------------------------------------------------------

static inline void run_gemm(const float* A, int lda, const float* W, int ldw,
                            const float* bias, float* out, int ldc,
                            int M, int N, int K, int splits, int relu,
                            float* part) {
    int Ksplit = K / splits;
    dim3 grid((N + 63) / 64, M / 64, splits);
    gemm_tf32_splitk<<<grid, 128>>>(A, lda, W, ldw, part, M, N, Ksplit);
    int tot = M * N;
    reduce_bias_kernel<<<(tot + 255) / 256, 256>>>(part, bias, out, ldc, M, N, splits, relu);
}

extern "C" void kernel_launch(void* const* d_in, const int* in_sizes, int n_in,
                              void* d_out, int out_size) {
    const float* node_feat = (const float*)d_in[0];
    const float* edge_feat = (const float*)d_in[1];
    const float* qemb      = (const float*)d_in[2];
    const int*   node_seg  = (const int*)d_in[3];
    const int*   edge_seg  = (const int*)d_in[4];
    const float* W_lang = (const float*)d_in[5];
    const float* b_lang = (const float*)d_in[6];
    const float* W_mid  = (const float*)d_in[7];
    const float* b_mid  = (const float*)d_in[8];
    const float* W_mid2 = (const float*)d_in[9];
    const float* b_mid2 = (const float*)d_in[10];
    const float* W_ans  = (const float*)d_in[11];
    const float* b_ans  = (const float*)d_in[12];

    const int N = in_sizes[3];   // num nodes
    const int E = in_sizes[4];   // num edges
    const int A = in_sizes[12];  // answer dim (3129)

    float *pooled, *mid, *mid2, *part;
    cudaGetSymbolAddress((void**)&pooled, g_pooled);
    cudaGetSymbolAddress((void**)&mid, g_mid);
    cudaGetSymbolAddress((void**)&mid2, g_mid2);
    cudaGetSymbolAddress((void**)&part, g_part);

    zero_pooled_kernel<<<(NGRAPH * C3H + 255) / 256, 256>>>();

    seg_sum_kernel<<<(N + SEG_ROWS - 1) / SEG_ROWS, 192>>>(node_feat, node_seg, N, 0);
    seg_sum_kernel<<<(E + SEG_ROWS - 1) / SEG_ROWS, 192>>>(edge_feat, edge_seg, E, HDIM);

    // lang = qemb @ W_lang + b_lang  -> pooled[:, 2H:3H]   (K=768, split 4)
    run_gemm(qemb, HDIM, W_lang, HDIM, b_lang, pooled + 2 * HDIM, C3H,
             NGRAPH, HDIM, HDIM, 4, 0, part);

    // mid = relu(pooled @ W_mid + b_mid)   K=2304, split 6
    run_gemm(pooled, C3H, W_mid, HDIM, b_mid, mid, HDIM,
             NGRAPH, HDIM, C3H, 6, 1, part);

    // mid2 = relu(mid @ W_mid2 + b_mid2)   K=768, split 4
    run_gemm(mid, HDIM, W_mid2, HDIM, b_mid2, mid2, HDIM,
             NGRAPH, HDIM, HDIM, 4, 1, part);

    // pred = mid2 @ W_ans + b_ans          N=3129, K=768, split 2
    run_gemm(mid2, HDIM, W_ans, A, b_ans, (float*)d_out, A,
             NGRAPH, A, HDIM, 2, 0, part);
}

// round 4
// speedup vs baseline: 1.2655x; 1.0243x over previous
#include <cuda_runtime.h>
#include <cstdint>

#define HDIM 768
#define NGRAPH 256
#define C3H (3 * HDIM)

// Scratch (allocation-free rule: __device__ globals)
__device__ float g_pooled[NGRAPH * C3H];   // [B, 3H]: nodes | edges | lang
__device__ float g_mid[NGRAPH * HDIM];
__device__ float g_mid2[NGRAPH * HDIM];
__device__ float g_part[4 * NGRAPH * 3129];  // split-K partials (max: ans, 4 splits)

__global__ void zero_pooled_kernel() {
    int i = blockIdx.x * blockDim.x + threadIdx.x;
    if (i < NGRAPH * C3H) g_pooled[i] = 0.f;
}

// ---------------------------------------------------------------------------
// Segment sum (unchanged: ~HBM roofline)
// ---------------------------------------------------------------------------
#define SEG_ROWS 512

__global__ void seg_sum_kernel(const float* __restrict__ feat,
                               const int* __restrict__ seg,
                               int n, int col_off) {
    const int tid = threadIdx.x;  // 0..191
    long r0 = (long)blockIdx.x * SEG_ROWS;
    long r1 = r0 + SEG_ROWS;
    if (r1 > n) r1 = n;
    if (r0 >= r1) return;

    const float* base = feat + tid * 4;
    float4 acc = make_float4(0.f, 0.f, 0.f, 0.f);
    int cur = __ldg(seg + r0);

    long r = r0;
    while (r + 4 <= r1) {
        int s3 = __ldg(seg + r + 3);
        float4 v0 = *reinterpret_cast<const float4*>(base + (r + 0) * HDIM);
        float4 v1 = *reinterpret_cast<const float4*>(base + (r + 1) * HDIM);
        float4 v2 = *reinterpret_cast<const float4*>(base + (r + 2) * HDIM);
        float4 v3 = *reinterpret_cast<const float4*>(base + (r + 3) * HDIM);
        if (s3 == cur) {
            acc.x += v0.x + v1.x + v2.x + v3.x;
            acc.y += v0.y + v1.y + v2.y + v3.y;
            acc.z += v0.z + v1.z + v2.z + v3.z;
            acc.w += v0.w + v1.w + v2.w + v3.w;
        } else {
            int s0 = __ldg(seg + r);
            int s1 = __ldg(seg + r + 1);
            int s2 = __ldg(seg + r + 2);
            float4 vs[4] = {v0, v1, v2, v3};
            int ss[4] = {s0, s1, s2, s3};
            #pragma unroll
            for (int q = 0; q < 4; q++) {
                if (ss[q] != cur) {
                    float* o = g_pooled + (long)cur * C3H + col_off + tid * 4;
                    atomicAdd(o + 0, acc.x);
                    atomicAdd(o + 1, acc.y);
                    atomicAdd(o + 2, acc.z);
                    atomicAdd(o + 3, acc.w);
                    acc = make_float4(0.f, 0.f, 0.f, 0.f);
                    cur = ss[q];
                }
                acc.x += vs[q].x; acc.y += vs[q].y;
                acc.z += vs[q].z; acc.w += vs[q].w;
            }
        }
        r += 4;
    }
    for (; r < r1; ++r) {
        int s = __ldg(seg + r);
        if (s != cur) {
            float* o = g_pooled + (long)cur * C3H + col_off + tid * 4;
            atomicAdd(o + 0, acc.x);
            atomicAdd(o + 1, acc.y);
            atomicAdd(o + 2, acc.z);
            atomicAdd(o + 3, acc.w);
            acc = make_float4(0.f, 0.f, 0.f, 0.f);
            cur = s;
        }
        float4 v = *reinterpret_cast<const float4*>(base + r * HDIM);
        acc.x += v.x; acc.y += v.y; acc.z += v.z; acc.w += v.w;
    }
    {
        float* o = g_pooled + (long)cur * C3H + col_off + tid * 4;
        atomicAdd(o + 0, acc.x);
        atomicAdd(o + 1, acc.y);
        atomicAdd(o + 2, acc.z);
        atomicAdd(o + 3, acc.w);
    }
}

// ---------------------------------------------------------------------------
// TF32 tensor-core GEMM, 3xTF32 decomposition, split-K, software-pipelined.
// BM=64, BN=128, BK=16; 256 threads = 8 warps (2 M x 4 N), warp tile 32x32.
// Double-buffered smem; next tile prefetched into regs during compute.
// Smem layouts (conflict-free fragment reads):
//   As[k][m]  pad 72 : bank = (8*tq + g) % 32  -> all 32 lanes distinct
//   Bs[n][k]  pad 20 : bank = (20*g + tq) % 32 -> all 32 lanes distinct
// ---------------------------------------------------------------------------
__device__ __forceinline__ void tf32split(float x, unsigned& hi, unsigned& lo) {
    unsigned h;
    asm("cvt.rna.tf32.f32 %0, %1;" : "=r"(h) : "f"(x));
    float hf = __uint_as_float(h);
    unsigned l;
    float d = x - hf;
    asm("cvt.rna.tf32.f32 %0, %1;" : "=r"(l) : "f"(d));
    hi = h; lo = l;
}

__device__ __forceinline__ void mma8(float* d, const unsigned* a, const unsigned* b) {
    asm("mma.sync.aligned.m16n8k8.row.col.f32.tf32.tf32.f32 "
        "{%0,%1,%2,%3},{%4,%5,%6,%7},{%8,%9},{%0,%1,%2,%3};"
        : "+f"(d[0]), "+f"(d[1]), "+f"(d[2]), "+f"(d[3])
        : "r"(a[0]), "r"(a[1]), "r"(a[2]), "r"(a[3]), "r"(b[0]), "r"(b[1]));
}

__global__ __launch_bounds__(256) void gemm_tf32_splitk(
    const float* __restrict__ A, int lda,
    const float* __restrict__ W, int ldw,
    float* __restrict__ part,
    int M, int N, int Ksplit) {
    __shared__ float As[2][16][72];
    __shared__ float Bs[2][128][20];

    const int t = threadIdx.x;          // 0..255
    const int wid = t >> 5;
    const int lane = t & 31;
    const int wm = (wid & 1) * 32;      // 2 warps along M (64)
    const int wn = (wid >> 1) * 32;     // 4 warps along N (128)
    const int bm = blockIdx.y * 64;
    const int bn = blockIdx.x * 128;
    const int g = lane >> 2;            // 0..7
    const int tq = lane & 3;            // 0..3

    const int kbeg = blockIdx.z * Ksplit;
    const int kend = kbeg + Ksplit;

    // A gmem mapping: 64x16 floats / 256 thr = 1 float4 each
    const int ar = t & 63;              // row 0..63
    const int ac = (t >> 6) * 4;        // k 0,4,8,12

    float4 areg;
    float breg[8];

    auto ld_tiles = [&](int k0) {
        areg = *reinterpret_cast<const float4*>(A + (long)(bm + ar) * lda + k0 + ac);
        #pragma unroll
        for (int i = 0; i < 8; i++) {
            int idx = t + i * 256;      // over 16x128
            int br = idx >> 7;          // k 0..15
            int bc = idx & 127;         // n 0..127
            int gn = bn + bc;
            breg[i] = (gn < N) ? __ldg(W + (long)(k0 + br) * ldw + gn) : 0.f;
        }
    };

    float acc[2][4][4] = {};

    ld_tiles(kbeg);
    int buf = 0;
    for (int k0 = kbeg; k0 < kend; k0 += 16) {
        // commit staged tile to smem
        As[buf][ac + 0][ar] = areg.x;
        As[buf][ac + 1][ar] = areg.y;
        As[buf][ac + 2][ar] = areg.z;
        As[buf][ac + 3][ar] = areg.w;
        #pragma unroll
        for (int i = 0; i < 8; i++) {
            int idx = t + i * 256;
            Bs[buf][idx & 127][idx >> 7] = breg[i];
        }
        __syncthreads();

        // prefetch next tile (LDGs in flight during compute)
        if (k0 + 16 < kend) ld_tiles(k0 + 16);

        #pragma unroll
        for (int kk = 0; kk < 16; kk += 8) {
            unsigned ah[2][4], al[2][4];
            #pragma unroll
            for (int mt = 0; mt < 2; mt++) {
                int row = wm + mt * 16 + g;
                tf32split(As[buf][kk + tq][row],         ah[mt][0], al[mt][0]);
                tf32split(As[buf][kk + tq][row + 8],     ah[mt][1], al[mt][1]);
                tf32split(As[buf][kk + tq + 4][row],     ah[mt][2], al[mt][2]);
                tf32split(As[buf][kk + tq + 4][row + 8], ah[mt][3], al[mt][3]);
            }
            unsigned bh[4][2], bl[4][2];
            #pragma unroll
            for (int nt = 0; nt < 4; nt++) {
                int col = wn + nt * 8 + g;
                tf32split(Bs[buf][col][kk + tq],     bh[nt][0], bl[nt][0]);
                tf32split(Bs[buf][col][kk + tq + 4], bh[nt][1], bl[nt][1]);
            }
            #pragma unroll
            for (int mt = 0; mt < 2; mt++) {
                #pragma unroll
                for (int nt = 0; nt < 4; nt++) {
                    mma8(acc[mt][nt], ah[mt], bl[nt]);   // hi*lo
                    mma8(acc[mt][nt], al[mt], bh[nt]);   // lo*hi
                    mma8(acc[mt][nt], ah[mt], bh[nt]);   // hi*hi
                }
            }
        }
        __syncthreads();   // protect buffer before next overwrite
        buf ^= 1;
    }

    const long sbase = (long)blockIdx.z * M;
    #pragma unroll
    for (int mt = 0; mt < 2; mt++) {
        int row = bm + wm + mt * 16 + g;
        #pragma unroll
        for (int nt = 0; nt < 4; nt++) {
            int col = bn + wn + nt * 8 + tq * 2;
            float* p0 = part + (sbase + row) * N + col;
            float* p1 = part + (sbase + row + 8) * N + col;
            if (col < N)     { p0[0] = acc[mt][nt][0]; p1[0] = acc[mt][nt][2]; }
            if (col + 1 < N) { p0[1] = acc[mt][nt][1]; p1[1] = acc[mt][nt][3]; }
        }
    }
}

// Reduce split-K partials + bias (+relu), write to out with row stride ldc.
__global__ void reduce_bias_kernel(const float* __restrict__ part,
                                   const float* __restrict__ bias,
                                   float* __restrict__ out, int ldc,
                                   int M, int N, int splits, int relu) {
    int i = blockIdx.x * blockDim.x + threadIdx.x;
    if (i >= M * N) return;
    int m = i / N, n = i - m * N;
    float s = __ldg(bias + n);
    for (int q = 0; q < splits; q++)
        s += part[((long)q * M + m) * N + n];
    if (relu) s = fmaxf(s, 0.f);
    out[(long)m * ldc + n] = s;
}

// ---------------------------------------------------------------------------

static inline void run_gemm(const float* A, int lda, const float* W, int ldw,
                            const float* bias, float* out, int ldc,
                            int M, int N, int K, int splits, int relu,
                            float* part) {
    int Ksplit = K / splits;
    dim3 grid((N + 127) / 128, M / 64, splits);
    gemm_tf32_splitk<<<grid, 256>>>(A, lda, W, ldw, part, M, N, Ksplit);
    int tot = M * N;
    reduce_bias_kernel<<<(tot + 255) / 256, 256>>>(part, bias, out, ldc, M, N, splits, relu);
}

extern "C" void kernel_launch(void* const* d_in, const int* in_sizes, int n_in,
                              void* d_out, int out_size) {
    const float* node_feat = (const float*)d_in[0];
    const float* edge_feat = (const float*)d_in[1];
    const float* qemb      = (const float*)d_in[2];
    const int*   node_seg  = (const int*)d_in[3];
    const int*   edge_seg  = (const int*)d_in[4];
    const float* W_lang = (const float*)d_in[5];
    const float* b_lang = (const float*)d_in[6];
    const float* W_mid  = (const float*)d_in[7];
    const float* b_mid  = (const float*)d_in[8];
    const float* W_mid2 = (const float*)d_in[9];
    const float* b_mid2 = (const float*)d_in[10];
    const float* W_ans  = (const float*)d_in[11];
    const float* b_ans  = (const float*)d_in[12];

    const int N = in_sizes[3];   // num nodes
    const int E = in_sizes[4];   // num edges
    const int A = in_sizes[12];  // answer dim (3129)

    float *pooled, *mid, *mid2, *part;
    cudaGetSymbolAddress((void**)&pooled, g_pooled);
    cudaGetSymbolAddress((void**)&mid, g_mid);
    cudaGetSymbolAddress((void**)&mid2, g_mid2);
    cudaGetSymbolAddress((void**)&part, g_part);

    zero_pooled_kernel<<<(NGRAPH * C3H + 255) / 256, 256>>>();

    seg_sum_kernel<<<(N + SEG_ROWS - 1) / SEG_ROWS, 192>>>(node_feat, node_seg, N, 0);
    seg_sum_kernel<<<(E + SEG_ROWS - 1) / SEG_ROWS, 192>>>(edge_feat, edge_seg, E, HDIM);

    // lang = qemb @ W_lang + b_lang  -> pooled[:, 2H:3H]  (grid 6x4, split 8 -> 192 blocks)
    run_gemm(qemb, HDIM, W_lang, HDIM, b_lang, pooled + 2 * HDIM, C3H,
             NGRAPH, HDIM, HDIM, 8, 0, part);

    // mid = relu(pooled @ W_mid + b_mid)   K=2304, split 8 -> 192 blocks
    run_gemm(pooled, C3H, W_mid, HDIM, b_mid, mid, HDIM,
             NGRAPH, HDIM, C3H, 8, 1, part);

    // mid2 = relu(mid @ W_mid2 + b_mid2)   split 8 -> 192 blocks
    run_gemm(mid, HDIM, W_mid2, HDIM, b_mid2, mid2, HDIM,
             NGRAPH, HDIM, HDIM, 8, 1, part);

    // pred = mid2 @ W_ans + b_ans          N=3129 (grid 25x4), split 4 -> 400 blocks
    run_gemm(mid2, HDIM, W_ans, A, b_ans, (float*)d_out, A,
             NGRAPH, A, HDIM, 4, 0, part);
}

// round 5
// speedup vs baseline: 1.3644x; 1.0781x over previous
#include <cuda_runtime.h>
#include <cstdint>

#define HDIM 768
#define NGRAPH 256
#define C3H (3 * HDIM)
#define SLOT (NGRAPH * HDIM)           // 196608 floats per [256,768] slot

// Scratch (allocation-free rule: __device__ globals)
__device__ float g_pooled[NGRAPH * C3H];   // [B, 3H]: nodes | edges | lang
__device__ float g_mid[NGRAPH * HDIM];
__device__ float g_mid2[NGRAPH * HDIM];
// partL: 8 slots (lang gemm, later mid2 gemm). partM: 18 slots (mid partials;
// later ans partials: 4*256*3129 = 3204096 <= 18*SLOT). Total 5111808 floats.
__device__ float g_part[5111808];

// Zero only node+edge columns (lang cols written directly by lang reduce on s1)
__global__ void zero_ne_kernel() {
    int i = blockIdx.x * blockDim.x + threadIdx.x;
    if (i < NGRAPH * 2 * HDIM) {
        int m = i / (2 * HDIM), c = i - m * (2 * HDIM);
        g_pooled[m * C3H + c] = 0.f;
    }
}

// ---------------------------------------------------------------------------
// Segment sum (unchanged: ~HBM roofline)
// ---------------------------------------------------------------------------
#define SEG_ROWS 512

__global__ void seg_sum_kernel(const float* __restrict__ feat,
                               const int* __restrict__ seg,
                               int n, int col_off) {
    const int tid = threadIdx.x;  // 0..191
    long r0 = (long)blockIdx.x * SEG_ROWS;
    long r1 = r0 + SEG_ROWS;
    if (r1 > n) r1 = n;
    if (r0 >= r1) return;

    const float* base = feat + tid * 4;
    float4 acc = make_float4(0.f, 0.f, 0.f, 0.f);
    int cur = __ldg(seg + r0);

    long r = r0;
    while (r + 4 <= r1) {
        int s3 = __ldg(seg + r + 3);
        float4 v0 = *reinterpret_cast<const float4*>(base + (r + 0) * HDIM);
        float4 v1 = *reinterpret_cast<const float4*>(base + (r + 1) * HDIM);
        float4 v2 = *reinterpret_cast<const float4*>(base + (r + 2) * HDIM);
        float4 v3 = *reinterpret_cast<const float4*>(base + (r + 3) * HDIM);
        if (s3 == cur) {
            acc.x += v0.x + v1.x + v2.x + v3.x;
            acc.y += v0.y + v1.y + v2.y + v3.y;
            acc.z += v0.z + v1.z + v2.z + v3.z;
            acc.w += v0.w + v1.w + v2.w + v3.w;
        } else {
            int s0 = __ldg(seg + r);
            int s1 = __ldg(seg + r + 1);
            int s2 = __ldg(seg + r + 2);
            float4 vs[4] = {v0, v1, v2, v3};
            int ss[4] = {s0, s1, s2, s3};
            #pragma unroll
            for (int q = 0; q < 4; q++) {
                if (ss[q] != cur) {
                    float* o = g_pooled + (long)cur * C3H + col_off + tid * 4;
                    atomicAdd(o + 0, acc.x);
                    atomicAdd(o + 1, acc.y);
                    atomicAdd(o + 2, acc.z);
                    atomicAdd(o + 3, acc.w);
                    acc = make_float4(0.f, 0.f, 0.f, 0.f);
                    cur = ss[q];
                }
                acc.x += vs[q].x; acc.y += vs[q].y;
                acc.z += vs[q].z; acc.w += vs[q].w;
            }
        }
        r += 4;
    }
    for (; r < r1; ++r) {
        int s = __ldg(seg + r);
        if (s != cur) {
            float* o = g_pooled + (long)cur * C3H + col_off + tid * 4;
            atomicAdd(o + 0, acc.x);
            atomicAdd(o + 1, acc.y);
            atomicAdd(o + 2, acc.z);
            atomicAdd(o + 3, acc.w);
            acc = make_float4(0.f, 0.f, 0.f, 0.f);
            cur = s;
        }
        float4 v = *reinterpret_cast<const float4*>(base + r * HDIM);
        acc.x += v.x; acc.y += v.y; acc.z += v.z; acc.w += v.w;
    }
    {
        float* o = g_pooled + (long)cur * C3H + col_off + tid * 4;
        atomicAdd(o + 0, acc.x);
        atomicAdd(o + 1, acc.y);
        atomicAdd(o + 2, acc.z);
        atomicAdd(o + 3, acc.w);
    }
}

// ---------------------------------------------------------------------------
// TF32 tensor-core GEMM, 3xTF32, split-K, pipelined, PRE-SPLIT hi/lo in smem.
// BM=64, BN=128, BK=16; 256 thr = 8 warps (2M x 4N), warp tile 32x32.
// Dynamic smem 53248 B:
//   As[buf][hl][16][72]  : bank (8*tq+g) -> conflict-free loads; seq stores CF
//   Bs[buf][hl][16][136] : bank (8*tq+..+g) -> conflict-free loads; seq stores CF
// Inner loop is pure LDS + MMA (splits done once per element at commit).
// ---------------------------------------------------------------------------
#define GEMM_SMEM_FLOATS (2*2*16*72 + 2*2*16*136)   // 13312 floats = 53248 B

__device__ __forceinline__ void tf32split(float x, unsigned& hi, unsigned& lo) {
    unsigned h;
    asm("cvt.rna.tf32.f32 %0, %1;" : "=r"(h) : "f"(x));
    float hf = __uint_as_float(h);
    unsigned l;
    float d = x - hf;
    asm("cvt.rna.tf32.f32 %0, %1;" : "=r"(l) : "f"(d));
    hi = h; lo = l;
}

__device__ __forceinline__ void mma8(float* d, const unsigned* a, const unsigned* b) {
    asm("mma.sync.aligned.m16n8k8.row.col.f32.tf32.tf32.f32 "
        "{%0,%1,%2,%3},{%4,%5,%6,%7},{%8,%9},{%0,%1,%2,%3};"
        : "+f"(d[0]), "+f"(d[1]), "+f"(d[2]), "+f"(d[3])
        : "r"(a[0]), "r"(a[1]), "r"(a[2]), "r"(a[3]), "r"(b[0]), "r"(b[1]));
}

__global__ __launch_bounds__(256) void gemm_tf32_splitk(
    const float* __restrict__ A, int lda,
    const float* __restrict__ W, int ldw,
    float* __restrict__ part,
    int M, int N, int Ksplit) {
    extern __shared__ float dynsmem[];
    float* AsB = dynsmem;                        // [2][2][16][72]
    float* BsB = dynsmem + 2 * 2 * 16 * 72;      // [2][2][16][136]
#define AS(b,h,k,m) AsB[((((b)*2+(h))*16+(k))*72)+(m)]
#define BS(b,h,k,n) BsB[((((b)*2+(h))*16+(k))*136)+(n)]

    const int t = threadIdx.x;          // 0..255
    const int wid = t >> 5;
    const int lane = t & 31;
    const int wm = (wid & 1) * 32;
    const int wn = (wid >> 1) * 32;
    const int bm = blockIdx.y * 64;
    const int bn = blockIdx.x * 128;
    const int g = lane >> 2;
    const int tq = lane & 3;

    const int kbeg = blockIdx.z * Ksplit;
    const int kend = kbeg + Ksplit;

    const int ar = t & 63;
    const int ac = (t >> 6) * 4;

    float4 areg;
    float breg[8];

    auto ld_tiles = [&](int k0) {
        areg = *reinterpret_cast<const float4*>(A + (long)(bm + ar) * lda + k0 + ac);
        #pragma unroll
        for (int i = 0; i < 8; i++) {
            int idx = t + i * 256;
            int br = idx >> 7;
            int bc = idx & 127;
            int gn = bn + bc;
            breg[i] = (gn < N) ? __ldg(W + (long)(k0 + br) * ldw + gn) : 0.f;
        }
    };

    float acc[2][4][4] = {};

    ld_tiles(kbeg);
    int buf = 0;
    for (int k0 = kbeg; k0 < kend; k0 += 16) {
        // commit + split once per element
        {
            float av[4] = {areg.x, areg.y, areg.z, areg.w};
            #pragma unroll
            for (int j = 0; j < 4; j++) {
                unsigned h, l; tf32split(av[j], h, l);
                AS(buf, 0, ac + j, ar) = __uint_as_float(h);
                AS(buf, 1, ac + j, ar) = __uint_as_float(l);
            }
            #pragma unroll
            for (int i = 0; i < 8; i++) {
                int idx = t + i * 256;
                int br = idx >> 7;
                int bc = idx & 127;
                unsigned h, l; tf32split(breg[i], h, l);
                BS(buf, 0, br, bc) = __uint_as_float(h);
                BS(buf, 1, br, bc) = __uint_as_float(l);
            }
        }
        __syncthreads();

        if (k0 + 16 < kend) ld_tiles(k0 + 16);

        #pragma unroll
        for (int kk = 0; kk < 16; kk += 8) {
            unsigned ah[2][4], al[2][4];
            #pragma unroll
            for (int mt = 0; mt < 2; mt++) {
                int row = wm + mt * 16 + g;
                ah[mt][0] = __float_as_uint(AS(buf, 0, kk + tq, row));
                al[mt][0] = __float_as_uint(AS(buf, 1, kk + tq, row));
                ah[mt][1] = __float_as_uint(AS(buf, 0, kk + tq, row + 8));
                al[mt][1] = __float_as_uint(AS(buf, 1, kk + tq, row + 8));
                ah[mt][2] = __float_as_uint(AS(buf, 0, kk + tq + 4, row));
                al[mt][2] = __float_as_uint(AS(buf, 1, kk + tq + 4, row));
                ah[mt][3] = __float_as_uint(AS(buf, 0, kk + tq + 4, row + 8));
                al[mt][3] = __float_as_uint(AS(buf, 1, kk + tq + 4, row + 8));
            }
            unsigned bh[4][2], bl[4][2];
            #pragma unroll
            for (int nt = 0; nt < 4; nt++) {
                int col = wn + nt * 8 + g;
                bh[nt][0] = __float_as_uint(BS(buf, 0, kk + tq, col));
                bl[nt][0] = __float_as_uint(BS(buf, 1, kk + tq, col));
                bh[nt][1] = __float_as_uint(BS(buf, 0, kk + tq + 4, col));
                bl[nt][1] = __float_as_uint(BS(buf, 1, kk + tq + 4, col));
            }
            #pragma unroll
            for (int mt = 0; mt < 2; mt++) {
                #pragma unroll
                for (int nt = 0; nt < 4; nt++) {
                    mma8(acc[mt][nt], ah[mt], bl[nt]);   // hi*lo
                    mma8(acc[mt][nt], al[mt], bh[nt]);   // lo*hi
                    mma8(acc[mt][nt], ah[mt], bh[nt]);   // hi*hi
                }
            }
        }
        __syncthreads();
        buf ^= 1;
    }

    const long sbase = (long)blockIdx.z * M;
    #pragma unroll
    for (int mt = 0; mt < 2; mt++) {
        int row = bm + wm + mt * 16 + g;
        #pragma unroll
        for (int nt = 0; nt < 4; nt++) {
            int col = bn + wn + nt * 8 + tq * 2;
            float* p0 = part + (sbase + row) * N + col;
            float* p1 = part + (sbase + row + 8) * N + col;
            if (col < N)     { p0[0] = acc[mt][nt][0]; p1[0] = acc[mt][nt][2]; }
            if (col + 1 < N) { p0[1] = acc[mt][nt][1]; p1[1] = acc[mt][nt][3]; }
        }
    }
#undef AS
#undef BS
}

// Reduce split-K partials + bias (+relu), write to out with row stride ldc.
__global__ void reduce_bias_kernel(const float* __restrict__ part,
                                   const float* __restrict__ bias,
                                   float* __restrict__ out, int ldc,
                                   int M, int N, int splits, int relu) {
    int i = blockIdx.x * blockDim.x + threadIdx.x;
    if (i >= M * N) return;
    int m = i / N, n = i - m * N;
    float s = __ldg(bias + n);
    for (int q = 0; q < splits; q++)
        s += part[((long)q * M + m) * N + n];
    if (relu) s = fmaxf(s, 0.f);
    out[(long)m * ldc + n] = s;
}

// ---------------------------------------------------------------------------

extern "C" void kernel_launch(void* const* d_in, const int* in_sizes, int n_in,
                              void* d_out, int out_size) {
    const float* node_feat = (const float*)d_in[0];
    const float* edge_feat = (const float*)d_in[1];
    const float* qemb      = (const float*)d_in[2];
    const int*   node_seg  = (const int*)d_in[3];
    const int*   edge_seg  = (const int*)d_in[4];
    const float* W_lang = (const float*)d_in[5];
    const float* b_lang = (const float*)d_in[6];
    const float* W_mid  = (const float*)d_in[7];
    const float* b_mid  = (const float*)d_in[8];
    const float* W_mid2 = (const float*)d_in[9];
    const float* b_mid2 = (const float*)d_in[10];
    const float* W_ans  = (const float*)d_in[11];
    const float* b_ans  = (const float*)d_in[12];

    const int N = in_sizes[3];
    const int E = in_sizes[4];
    const int A = in_sizes[12];   // 3129
    const int SMB = GEMM_SMEM_FLOATS * 4;

    float *pooled, *mid, *mid2, *part;
    cudaGetSymbolAddress((void**)&pooled, g_pooled);
    cudaGetSymbolAddress((void**)&mid, g_mid);
    cudaGetSymbolAddress((void**)&mid2, g_mid2);
    cudaGetSymbolAddress((void**)&part, g_part);
    float* partL = part;                 // 8 slots
    float* partM = part + 8 * SLOT;      // 18 slots (mid: nodes 0-5, edges 6-11, lang 12-17)

    // One-time stream/event/attr setup (correctness run happens uncaptured first)
    static cudaStream_t s1 = nullptr, s2 = nullptr;
    static cudaEvent_t evFork, evN, evMN, evML;
    if (!s1) {
        cudaStreamCreateWithFlags(&s1, cudaStreamNonBlocking);
        cudaStreamCreateWithFlags(&s2, cudaStreamNonBlocking);
        cudaEventCreateWithFlags(&evFork, cudaEventDisableTiming);
        cudaEventCreateWithFlags(&evN, cudaEventDisableTiming);
        cudaEventCreateWithFlags(&evMN, cudaEventDisableTiming);
        cudaEventCreateWithFlags(&evML, cudaEventDisableTiming);
        cudaFuncSetAttribute(gemm_tf32_splitk,
                             cudaFuncAttributeMaxDynamicSharedMemorySize, SMB);
    }

    // Fork s1 (lang chain: independent of seg-sums)
    cudaEventRecord(evFork, 0);
    cudaStreamWaitEvent(s1, evFork, 0);

    // s1: lang = qemb @ W_lang + b_lang -> pooled[:, 2H:3H]  (splits 8)
    gemm_tf32_splitk<<<dim3(6, 4, 8), 256, SMB, s1>>>(
        qemb, HDIM, W_lang, HDIM, partL, NGRAPH, HDIM, 96);
    reduce_bias_kernel<<<(NGRAPH * HDIM + 255) / 256, 256, 0, s1>>>(
        partL, b_lang, pooled + 2 * HDIM, C3H, NGRAPH, HDIM, 8, 0);
    // s1: mid_lang partial = lang @ W_mid[1536:2304] -> partM slots 12..17
    gemm_tf32_splitk<<<dim3(6, 4, 6), 256, SMB, s1>>>(
        pooled + 2 * HDIM, C3H, W_mid + 2 * HDIM * HDIM, HDIM,
        partM + 12 * SLOT, NGRAPH, HDIM, 128);
    cudaEventRecord(evML, s1);

    // s0: zero node/edge cols, then the two seg-sums (HBM-bound)
    zero_ne_kernel<<<(NGRAPH * 2 * HDIM + 255) / 256, 256>>>();
    seg_sum_kernel<<<(N + SEG_ROWS - 1) / SEG_ROWS, 192>>>(node_feat, node_seg, N, 0);
    cudaEventRecord(evN, 0);
    seg_sum_kernel<<<(E + SEG_ROWS - 1) / SEG_ROWS, 192>>>(edge_feat, edge_seg, E, HDIM);

    // s2: mid_nodes partial after node seg-sum (overlaps edge seg-sum)
    cudaStreamWaitEvent(s2, evN, 0);
    gemm_tf32_splitk<<<dim3(6, 4, 6), 256, SMB, s2>>>(
        pooled, C3H, W_mid, HDIM, partM, NGRAPH, HDIM, 128);
    cudaEventRecord(evMN, s2);

    // s0: mid_edges partial right after edge seg-sum
    gemm_tf32_splitk<<<dim3(6, 4, 6), 256, SMB>>>(
        pooled + HDIM, C3H, W_mid + HDIM * HDIM, HDIM,
        partM + 6 * SLOT, NGRAPH, HDIM, 128);

    // join, then tail on s0
    cudaStreamWaitEvent(0, evMN, 0);
    cudaStreamWaitEvent(0, evML, 0);
    reduce_bias_kernel<<<(NGRAPH * HDIM + 255) / 256, 256>>>(
        partM, b_mid, mid, HDIM, NGRAPH, HDIM, 18, 1);

    // mid2 = relu(mid @ W_mid2 + b_mid2)  (reuse partL; s1 done per evML)
    gemm_tf32_splitk<<<dim3(6, 4, 8), 256, SMB>>>(
        mid, HDIM, W_mid2, HDIM, partL, NGRAPH, HDIM, 96);
    reduce_bias_kernel<<<(NGRAPH * HDIM + 255) / 256, 256>>>(
        partL, b_mid2, mid2, HDIM, NGRAPH, HDIM, 8, 1);

    // pred = mid2 @ W_ans + b_ans  (reuse partM region; splits 4)
    gemm_tf32_splitk<<<dim3(25, 4, 4), 256, SMB>>>(
        mid2, HDIM, W_ans, A, partM, NGRAPH, A, 192);
    reduce_bias_kernel<<<(NGRAPH * A + 255) / 256, 256>>>(
        partM, b_ans, (float*)d_out, A, NGRAPH, A, 4, 0);
}

// round 6
// speedup vs baseline: 1.4230x; 1.0430x over previous
#include <cuda_runtime.h>
#include <cstdint>

#define HDIM 768
#define NGRAPH 256
#define C3H (3 * HDIM)
#define SLOT (NGRAPH * HDIM)

// Scratch (allocation-free rule: __device__ globals)
__device__ float g_pooled[NGRAPH * C3H];   // [B, 3H]: nodes | edges | lang
__device__ float g_mid[NGRAPH * HDIM];     // pre-relu mid accumulator (bias-init)
__device__ float g_mid2[NGRAPH * HDIM];    // pre-relu mid2 accumulator (bias-init)

// One init kernel: pooled node/edge cols = 0, lang cols = b_lang;
// mid = b_mid; mid2 = b_mid2; d_out = b_ans (broadcast).
__global__ void init_kernel(const float* __restrict__ b_lang,
                            const float* __restrict__ b_mid,
                            const float* __restrict__ b_mid2,
                            const float* __restrict__ b_ans,
                            float* __restrict__ out, int A) {
    const int n_pooled = NGRAPH * C3H;
    const int n_out = NGRAPH * A;
    int total = n_pooled + 2 * SLOT + n_out;
    for (int i = blockIdx.x * blockDim.x + threadIdx.x; i < total;
         i += gridDim.x * blockDim.x) {
        if (i < n_pooled) {
            int c = i % C3H;
            g_pooled[i] = (c >= 2 * HDIM) ? __ldg(b_lang + c - 2 * HDIM) : 0.f;
        } else if (i < n_pooled + SLOT) {
            int j = i - n_pooled;
            g_mid[j] = __ldg(b_mid + (j % HDIM));
        } else if (i < n_pooled + 2 * SLOT) {
            int j = i - n_pooled - SLOT;
            g_mid2[j] = __ldg(b_mid2 + (j % HDIM));
        } else {
            int j = i - n_pooled - 2 * SLOT;
            out[j] = __ldg(b_ans + (j % A));
        }
    }
}

// ---------------------------------------------------------------------------
// Segment sum (unchanged: ~HBM roofline)
// ---------------------------------------------------------------------------
#define SEG_ROWS 512

__global__ void seg_sum_kernel(const float* __restrict__ feat,
                               const int* __restrict__ seg,
                               int n, int col_off) {
    const int tid = threadIdx.x;  // 0..191
    long r0 = (long)blockIdx.x * SEG_ROWS;
    long r1 = r0 + SEG_ROWS;
    if (r1 > n) r1 = n;
    if (r0 >= r1) return;

    const float* base = feat + tid * 4;
    float4 acc = make_float4(0.f, 0.f, 0.f, 0.f);
    int cur = __ldg(seg + r0);

    long r = r0;
    while (r + 4 <= r1) {
        int s3 = __ldg(seg + r + 3);
        float4 v0 = *reinterpret_cast<const float4*>(base + (r + 0) * HDIM);
        float4 v1 = *reinterpret_cast<const float4*>(base + (r + 1) * HDIM);
        float4 v2 = *reinterpret_cast<const float4*>(base + (r + 2) * HDIM);
        float4 v3 = *reinterpret_cast<const float4*>(base + (r + 3) * HDIM);
        if (s3 == cur) {
            acc.x += v0.x + v1.x + v2.x + v3.x;
            acc.y += v0.y + v1.y + v2.y + v3.y;
            acc.z += v0.z + v1.z + v2.z + v3.z;
            acc.w += v0.w + v1.w + v2.w + v3.w;
        } else {
            int s0 = __ldg(seg + r);
            int s1 = __ldg(seg + r + 1);
            int s2 = __ldg(seg + r + 2);
            float4 vs[4] = {v0, v1, v2, v3};
            int ss[4] = {s0, s1, s2, s3};
            #pragma unroll
            for (int q = 0; q < 4; q++) {
                if (ss[q] != cur) {
                    float* o = g_pooled + (long)cur * C3H + col_off + tid * 4;
                    atomicAdd(o + 0, acc.x);
                    atomicAdd(o + 1, acc.y);
                    atomicAdd(o + 2, acc.z);
                    atomicAdd(o + 3, acc.w);
                    acc = make_float4(0.f, 0.f, 0.f, 0.f);
                    cur = ss[q];
                }
                acc.x += vs[q].x; acc.y += vs[q].y;
                acc.z += vs[q].z; acc.w += vs[q].w;
            }
        }
        r += 4;
    }
    for (; r < r1; ++r) {
        int s = __ldg(seg + r);
        if (s != cur) {
            float* o = g_pooled + (long)cur * C3H + col_off + tid * 4;
            atomicAdd(o + 0, acc.x);
            atomicAdd(o + 1, acc.y);
            atomicAdd(o + 2, acc.z);
            atomicAdd(o + 3, acc.w);
            acc = make_float4(0.f, 0.f, 0.f, 0.f);
            cur = s;
        }
        float4 v = *reinterpret_cast<const float4*>(base + r * HDIM);
        acc.x += v.x; acc.y += v.y; acc.z += v.z; acc.w += v.w;
    }
    {
        float* o = g_pooled + (long)cur * C3H + col_off + tid * 4;
        atomicAdd(o + 0, acc.x);
        atomicAdd(o + 1, acc.y);
        atomicAdd(o + 2, acc.z);
        atomicAdd(o + 3, acc.w);
    }
}

// ---------------------------------------------------------------------------
// TF32 tensor-core GEMM, 3xTF32, split-K with ATOMIC accumulation into a
// bias-initialized destination. Optional relu applied to A at load time.
// BM=64, BN=128, BK=16; 256 thr = 8 warps (2M x 4N), warp tile 32x32.
// Pre-split hi/lo stored in double-buffered dynamic smem (conflict-free).
// ---------------------------------------------------------------------------
#define GEMM_SMEM_FLOATS (2*2*16*72 + 2*2*16*136)   // 53248 B

__device__ __forceinline__ void tf32split(float x, unsigned& hi, unsigned& lo) {
    unsigned h;
    asm("cvt.rna.tf32.f32 %0, %1;" : "=r"(h) : "f"(x));
    float hf = __uint_as_float(h);
    unsigned l;
    float d = x - hf;
    asm("cvt.rna.tf32.f32 %0, %1;" : "=r"(l) : "f"(d));
    hi = h; lo = l;
}

__device__ __forceinline__ void mma8(float* d, const unsigned* a, const unsigned* b) {
    asm("mma.sync.aligned.m16n8k8.row.col.f32.tf32.tf32.f32 "
        "{%0,%1,%2,%3},{%4,%5,%6,%7},{%8,%9},{%0,%1,%2,%3};"
        : "+f"(d[0]), "+f"(d[1]), "+f"(d[2]), "+f"(d[3])
        : "r"(a[0]), "r"(a[1]), "r"(a[2]), "r"(a[3]), "r"(b[0]), "r"(b[1]));
}

template <bool RELU_A>
__global__ __launch_bounds__(256) void gemm_tf32_atomic(
    const float* __restrict__ A, int lda,
    const float* __restrict__ W, int ldw,
    float* __restrict__ out, int ldc,
    int M, int N, int Ksplit) {
    extern __shared__ float dynsmem[];
    float* AsB = dynsmem;                        // [2][2][16][72]
    float* BsB = dynsmem + 2 * 2 * 16 * 72;      // [2][2][16][136]
#define AS(b,h,k,m) AsB[((((b)*2+(h))*16+(k))*72)+(m)]
#define BS(b,h,k,n) BsB[((((b)*2+(h))*16+(k))*136)+(n)]

    const int t = threadIdx.x;
    const int wid = t >> 5;
    const int lane = t & 31;
    const int wm = (wid & 1) * 32;
    const int wn = (wid >> 1) * 32;
    const int bm = blockIdx.y * 64;
    const int bn = blockIdx.x * 128;
    const int g = lane >> 2;
    const int tq = lane & 3;

    const int kbeg = blockIdx.z * Ksplit;
    const int kend = kbeg + Ksplit;

    const int ar = t & 63;
    const int ac = (t >> 6) * 4;

    float4 areg;
    float breg[8];

    auto ld_tiles = [&](int k0) {
        areg = *reinterpret_cast<const float4*>(A + (long)(bm + ar) * lda + k0 + ac);
        #pragma unroll
        for (int i = 0; i < 8; i++) {
            int idx = t + i * 256;
            int br = idx >> 7;
            int bc = idx & 127;
            int gn = bn + bc;
            breg[i] = (gn < N) ? __ldg(W + (long)(k0 + br) * ldw + gn) : 0.f;
        }
    };

    float acc[2][4][4] = {};

    ld_tiles(kbeg);
    int buf = 0;
    for (int k0 = kbeg; k0 < kend; k0 += 16) {
        {
            float av[4] = {areg.x, areg.y, areg.z, areg.w};
            #pragma unroll
            for (int j = 0; j < 4; j++) {
                float v = av[j];
                if (RELU_A) v = fmaxf(v, 0.f);
                unsigned h, l; tf32split(v, h, l);
                AS(buf, 0, ac + j, ar) = __uint_as_float(h);
                AS(buf, 1, ac + j, ar) = __uint_as_float(l);
            }
            #pragma unroll
            for (int i = 0; i < 8; i++) {
                int idx = t + i * 256;
                int br = idx >> 7;
                int bc = idx & 127;
                unsigned h, l; tf32split(breg[i], h, l);
                BS(buf, 0, br, bc) = __uint_as_float(h);
                BS(buf, 1, br, bc) = __uint_as_float(l);
            }
        }
        __syncthreads();

        if (k0 + 16 < kend) ld_tiles(k0 + 16);

        #pragma unroll
        for (int kk = 0; kk < 16; kk += 8) {
            unsigned ah[2][4], al[2][4];
            #pragma unroll
            for (int mt = 0; mt < 2; mt++) {
                int row = wm + mt * 16 + g;
                ah[mt][0] = __float_as_uint(AS(buf, 0, kk + tq, row));
                al[mt][0] = __float_as_uint(AS(buf, 1, kk + tq, row));
                ah[mt][1] = __float_as_uint(AS(buf, 0, kk + tq, row + 8));
                al[mt][1] = __float_as_uint(AS(buf, 1, kk + tq, row + 8));
                ah[mt][2] = __float_as_uint(AS(buf, 0, kk + tq + 4, row));
                al[mt][2] = __float_as_uint(AS(buf, 1, kk + tq + 4, row));
                ah[mt][3] = __float_as_uint(AS(buf, 0, kk + tq + 4, row + 8));
                al[mt][3] = __float_as_uint(AS(buf, 1, kk + tq + 4, row + 8));
            }
            unsigned bh[4][2], bl[4][2];
            #pragma unroll
            for (int nt = 0; nt < 4; nt++) {
                int col = wn + nt * 8 + g;
                bh[nt][0] = __float_as_uint(BS(buf, 0, kk + tq, col));
                bl[nt][0] = __float_as_uint(BS(buf, 1, kk + tq, col));
                bh[nt][1] = __float_as_uint(BS(buf, 0, kk + tq + 4, col));
                bl[nt][1] = __float_as_uint(BS(buf, 1, kk + tq + 4, col));
            }
            #pragma unroll
            for (int mt = 0; mt < 2; mt++) {
                #pragma unroll
                for (int nt = 0; nt < 4; nt++) {
                    mma8(acc[mt][nt], ah[mt], bl[nt]);   // hi*lo
                    mma8(acc[mt][nt], al[mt], bh[nt]);   // lo*hi
                    mma8(acc[mt][nt], ah[mt], bh[nt]);   // hi*hi
                }
            }
        }
        __syncthreads();
        buf ^= 1;
    }

    // Atomic accumulate into bias-initialized destination
    #pragma unroll
    for (int mt = 0; mt < 2; mt++) {
        int row = bm + wm + mt * 16 + g;
        #pragma unroll
        for (int nt = 0; nt < 4; nt++) {
            int col = bn + wn + nt * 8 + tq * 2;
            float* p0 = out + (long)row * ldc + col;
            float* p1 = out + (long)(row + 8) * ldc + col;
            if (col < N) {
                atomicAdd(p0, acc[mt][nt][0]);
                atomicAdd(p1, acc[mt][nt][2]);
            }
            if (col + 1 < N) {
                atomicAdd(p0 + 1, acc[mt][nt][1]);
                atomicAdd(p1 + 1, acc[mt][nt][3]);
            }
        }
    }
#undef AS
#undef BS
}

// ---------------------------------------------------------------------------

extern "C" void kernel_launch(void* const* d_in, const int* in_sizes, int n_in,
                              void* d_out, int out_size) {
    const float* node_feat = (const float*)d_in[0];
    const float* edge_feat = (const float*)d_in[1];
    const float* qemb      = (const float*)d_in[2];
    const int*   node_seg  = (const int*)d_in[3];
    const int*   edge_seg  = (const int*)d_in[4];
    const float* W_lang = (const float*)d_in[5];
    const float* b_lang = (const float*)d_in[6];
    const float* W_mid  = (const float*)d_in[7];
    const float* b_mid  = (const float*)d_in[8];
    const float* W_mid2 = (const float*)d_in[9];
    const float* b_mid2 = (const float*)d_in[10];
    const float* W_ans  = (const float*)d_in[11];
    const float* b_ans  = (const float*)d_in[12];

    const int N = in_sizes[3];
    const int E = in_sizes[4];
    const int A = in_sizes[12];   // 3129
    const int SMB = GEMM_SMEM_FLOATS * 4;

    float *pooled, *mid, *mid2;
    cudaGetSymbolAddress((void**)&pooled, g_pooled);
    cudaGetSymbolAddress((void**)&mid, g_mid);
    cudaGetSymbolAddress((void**)&mid2, g_mid2);

    static cudaStream_t s1 = nullptr, s2 = nullptr;
    static cudaEvent_t evFork, evN, evMN, evML;
    if (!s1) {
        cudaStreamCreateWithFlags(&s1, cudaStreamNonBlocking);
        cudaStreamCreateWithFlags(&s2, cudaStreamNonBlocking);
        cudaEventCreateWithFlags(&evFork, cudaEventDisableTiming);
        cudaEventCreateWithFlags(&evN, cudaEventDisableTiming);
        cudaEventCreateWithFlags(&evMN, cudaEventDisableTiming);
        cudaEventCreateWithFlags(&evML, cudaEventDisableTiming);
        cudaFuncSetAttribute(gemm_tf32_atomic<false>,
                             cudaFuncAttributeMaxDynamicSharedMemorySize, SMB);
        cudaFuncSetAttribute(gemm_tf32_atomic<true>,
                             cudaFuncAttributeMaxDynamicSharedMemorySize, SMB);
    }

    // s0: init all destinations with biases / zeros
    init_kernel<<<592, 256>>>(b_lang, b_mid, b_mid2, b_ans, (float*)d_out, A);
    cudaEventRecord(evFork, 0);
    cudaStreamWaitEvent(s1, evFork, 0);

    // s1 (overlaps seg-sums): lang += qemb @ W_lang -> pooled[:, 2H:3H]
    gemm_tf32_atomic<false><<<dim3(6, 4, 12), 256, SMB, s1>>>(
        qemb, HDIM, W_lang, HDIM, pooled + 2 * HDIM, C3H, NGRAPH, HDIM, 64);
    // s1: mid += lang @ W_mid[1536:2304]
    gemm_tf32_atomic<false><<<dim3(6, 4, 12), 256, SMB, s1>>>(
        pooled + 2 * HDIM, C3H, W_mid + 2 * HDIM * HDIM, HDIM,
        mid, HDIM, NGRAPH, HDIM, 64);
    cudaEventRecord(evML, s1);

    // s0: the two seg-sums (HBM-bound)
    seg_sum_kernel<<<(N + SEG_ROWS - 1) / SEG_ROWS, 192>>>(node_feat, node_seg, N, 0);
    cudaEventRecord(evN, 0);
    seg_sum_kernel<<<(E + SEG_ROWS - 1) / SEG_ROWS, 192>>>(edge_feat, edge_seg, E, HDIM);

    // s2: mid += nodes @ W_mid[0:768]   (overlaps edge seg-sum)
    cudaStreamWaitEvent(s2, evN, 0);
    gemm_tf32_atomic<false><<<dim3(6, 4, 12), 256, SMB, s2>>>(
        pooled, C3H, W_mid, HDIM, mid, HDIM, NGRAPH, HDIM, 64);
    cudaEventRecord(evMN, s2);

    // s0: mid += edges @ W_mid[768:1536]
    gemm_tf32_atomic<false><<<dim3(6, 4, 12), 256, SMB>>>(
        pooled + HDIM, C3H, W_mid + HDIM * HDIM, HDIM, mid, HDIM, NGRAPH, HDIM, 64);

    // join; tail on s0
    cudaStreamWaitEvent(0, evMN, 0);
    cudaStreamWaitEvent(0, evML, 0);

    // mid2 += relu(mid) @ W_mid2
    gemm_tf32_atomic<true><<<dim3(6, 4, 12), 256, SMB>>>(
        mid, HDIM, W_mid2, HDIM, mid2, HDIM, NGRAPH, HDIM, 64);

    // d_out += relu(mid2) @ W_ans
    gemm_tf32_atomic<true><<<dim3(25, 4, 6), 256, SMB>>>(
        mid2, HDIM, W_ans, A, (float*)d_out, A, NGRAPH, A, 128);
}

// round 8
// speedup vs baseline: 1.4866x; 1.0447x over previous
#include <cuda_runtime.h>
#include <cstdint>

#define HDIM 768
#define NGRAPH 256
#define C3H (3 * HDIM)
#define SLOT (NGRAPH * HDIM)

__device__ float g_pooled[NGRAPH * C3H];   // [B, 3H]: nodes | edges | lang
__device__ float g_mid[NGRAPH * HDIM];     // pre-relu mid accumulator (bias-init)
__device__ float g_mid2[NGRAPH * HDIM];    // pre-relu mid2 accumulator (bias-init)

// pooled node/edge cols = 0, lang cols = b_lang; mid = b_mid; mid2 = b_mid2.
__global__ void init_kernel(const float* __restrict__ b_lang,
                            const float* __restrict__ b_mid,
                            const float* __restrict__ b_mid2) {
    const int n_pooled = NGRAPH * C3H;
    int total = n_pooled + 2 * SLOT;
    for (int i = blockIdx.x * blockDim.x + threadIdx.x; i < total;
         i += gridDim.x * blockDim.x) {
        if (i < n_pooled) {
            int c = i % C3H;
            g_pooled[i] = (c >= 2 * HDIM) ? __ldg(b_lang + c - 2 * HDIM) : 0.f;
        } else if (i < n_pooled + SLOT) {
            int j = i - n_pooled;
            g_mid[j] = __ldg(b_mid + (j % HDIM));
        } else {
            int j = i - n_pooled - SLOT;
            g_mid2[j] = __ldg(b_mid2 + (j % HDIM));
        }
    }
}

// d_out = b_ans broadcast (side stream, off critical path)
__global__ void out_init_kernel(const float* __restrict__ b_ans,
                                float* __restrict__ out, int A) {
    int total = NGRAPH * A;
    for (int i = blockIdx.x * blockDim.x + threadIdx.x; i < total;
         i += gridDim.x * blockDim.x)
        out[i] = __ldg(b_ans + (i % A));
}

// ---------------------------------------------------------------------------
// Segment sums (sorted ids). Register accumulation, atomic flush on change.
// ---------------------------------------------------------------------------
#define SEG_ROWS 256

__global__ void seg_sum_full(const float* __restrict__ feat,
                             const int* __restrict__ seg,
                             int n, int col_off) {
    const int tid = threadIdx.x;  // 0..191
    long r0 = (long)blockIdx.x * SEG_ROWS;
    long r1 = r0 + SEG_ROWS;
    if (r1 > n) r1 = n;
    if (r0 >= r1) return;

    const float* base = feat + tid * 4;
    float4 acc = make_float4(0.f, 0.f, 0.f, 0.f);
    int cur = __ldg(seg + r0);

    long r = r0;
    while (r + 8 <= r1) {
        int s7 = __ldg(seg + r + 7);
        float4 v[8];
        #pragma unroll
        for (int q = 0; q < 8; q++)
            v[q] = __ldcs(reinterpret_cast<const float4*>(base + (r + q) * HDIM));
        if (s7 == cur) {
            #pragma unroll
            for (int q = 0; q < 8; q++) {
                acc.x += v[q].x; acc.y += v[q].y;
                acc.z += v[q].z; acc.w += v[q].w;
            }
        } else {
            #pragma unroll
            for (int q = 0; q < 8; q++) {
                int s = __ldg(seg + r + q);
                if (s != cur) {
                    float* o = g_pooled + (long)cur * C3H + col_off + tid * 4;
                    atomicAdd(o + 0, acc.x); atomicAdd(o + 1, acc.y);
                    atomicAdd(o + 2, acc.z); atomicAdd(o + 3, acc.w);
                    acc = make_float4(0.f, 0.f, 0.f, 0.f);
                    cur = s;
                }
                acc.x += v[q].x; acc.y += v[q].y;
                acc.z += v[q].z; acc.w += v[q].w;
            }
        }
        r += 8;
    }
    for (; r < r1; ++r) {
        int s = __ldg(seg + r);
        if (s != cur) {
            float* o = g_pooled + (long)cur * C3H + col_off + tid * 4;
            atomicAdd(o + 0, acc.x); atomicAdd(o + 1, acc.y);
            atomicAdd(o + 2, acc.z); atomicAdd(o + 3, acc.w);
            acc = make_float4(0.f, 0.f, 0.f, 0.f);
            cur = s;
        }
        float4 v = __ldcs(reinterpret_cast<const float4*>(base + r * HDIM));
        acc.x += v.x; acc.y += v.y; acc.z += v.z; acc.w += v.w;
    }
    {
        float* o = g_pooled + (long)cur * C3H + col_off + tid * 4;
        atomicAdd(o + 0, acc.x); atomicAdd(o + 1, acc.y);
        atomicAdd(o + 2, acc.z); atomicAdd(o + 3, acc.w);
    }
}

// Half-row variant: cols [c0, c0+384), 192 thr x float2.
__global__ void seg_sum_half(const float* __restrict__ feat,
                             const int* __restrict__ seg,
                             int n, int c0, int col_off) {
    const int tid = threadIdx.x;  // 0..191
    long r0 = (long)blockIdx.x * SEG_ROWS;
    long r1 = r0 + SEG_ROWS;
    if (r1 > n) r1 = n;
    if (r0 >= r1) return;

    const float* base = feat + c0 + tid * 2;
    float2 acc = make_float2(0.f, 0.f);
    int cur = __ldg(seg + r0);

    long r = r0;
    while (r + 8 <= r1) {
        int s7 = __ldg(seg + r + 7);
        float2 v[8];
        #pragma unroll
        for (int q = 0; q < 8; q++)
            v[q] = __ldcs(reinterpret_cast<const float2*>(base + (r + q) * HDIM));
        if (s7 == cur) {
            #pragma unroll
            for (int q = 0; q < 8; q++) { acc.x += v[q].x; acc.y += v[q].y; }
        } else {
            #pragma unroll
            for (int q = 0; q < 8; q++) {
                int s = __ldg(seg + r + q);
                if (s != cur) {
                    float* o = g_pooled + (long)cur * C3H + col_off + tid * 2;
                    atomicAdd(o + 0, acc.x); atomicAdd(o + 1, acc.y);
                    acc = make_float2(0.f, 0.f);
                    cur = s;
                }
                acc.x += v[q].x; acc.y += v[q].y;
            }
        }
        r += 8;
    }
    for (; r < r1; ++r) {
        int s = __ldg(seg + r);
        if (s != cur) {
            float* o = g_pooled + (long)cur * C3H + col_off + tid * 2;
            atomicAdd(o + 0, acc.x); atomicAdd(o + 1, acc.y);
            acc = make_float2(0.f, 0.f);
            cur = s;
        }
        float2 v = __ldcs(reinterpret_cast<const float2*>(base + r * HDIM));
        acc.x += v.x; acc.y += v.y;
    }
    {
        float* o = g_pooled + (long)cur * C3H + col_off + tid * 2;
        atomicAdd(o + 0, acc.x); atomicAdd(o + 1, acc.y);
    }
}

// ---------------------------------------------------------------------------
// TF32 tensor-core GEMM, 3xTF32, split-K, atomic accumulation into
// bias-initialized destination. Optional relu on A at load.
// ---------------------------------------------------------------------------
#define GEMM_SMEM_FLOATS (2*2*16*72 + 2*2*16*136)   // 53248 B

__device__ __forceinline__ void tf32split(float x, unsigned& hi, unsigned& lo) {
    unsigned h;
    asm("cvt.rna.tf32.f32 %0, %1;" : "=r"(h) : "f"(x));
    float hf = __uint_as_float(h);
    unsigned l;
    float d = x - hf;
    asm("cvt.rna.tf32.f32 %0, %1;" : "=r"(l) : "f"(d));
    hi = h; lo = l;
}

__device__ __forceinline__ void mma8(float* d, const unsigned* a, const unsigned* b) {
    asm("mma.sync.aligned.m16n8k8.row.col.f32.tf32.tf32.f32 "
        "{%0,%1,%2,%3},{%4,%5,%6,%7},{%8,%9},{%0,%1,%2,%3};"
        : "+f"(d[0]), "+f"(d[1]), "+f"(d[2]), "+f"(d[3])
        : "r"(a[0]), "r"(a[1]), "r"(a[2]), "r"(a[3]), "r"(b[0]), "r"(b[1]));
}

template <bool RELU_A>
__global__ __launch_bounds__(256) void gemm_tf32_atomic(
    const float* __restrict__ A, int lda,
    const float* __restrict__ W, int ldw,
    float* __restrict__ out, int ldc,
    int M, int N, int Ksplit) {
    extern __shared__ float dynsmem[];
    float* AsB = dynsmem;                        // [2][2][16][72]
    float* BsB = dynsmem + 2 * 2 * 16 * 72;      // [2][2][16][136]
#define AS(b,h,k,m) AsB[((((b)*2+(h))*16+(k))*72)+(m)]
#define BS(b,h,k,n) BsB[((((b)*2+(h))*16+(k))*136)+(n)]

    const int t = threadIdx.x;
    const int wid = t >> 5;
    const int lane = t & 31;
    const int wm = (wid & 1) * 32;
    const int wn = (wid >> 1) * 32;
    const int bm = blockIdx.y * 64;
    const int bn = blockIdx.x * 128;
    const int g = lane >> 2;
    const int tq = lane & 3;

    const int kbeg = blockIdx.z * Ksplit;
    const int kend = kbeg + Ksplit;

    const int ar = t & 63;
    const int ac = (t >> 6) * 4;

    float4 areg;
    float breg[8];

    auto ld_tiles = [&](int k0) {
        areg = *reinterpret_cast<const float4*>(A + (long)(bm + ar) * lda + k0 + ac);
        #pragma unroll
        for (int i = 0; i < 8; i++) {
            int idx = t + i * 256;
            int br = idx >> 7;
            int bc = idx & 127;
            int gn = bn + bc;
            breg[i] = (gn < N) ? __ldg(W + (long)(k0 + br) * ldw + gn) : 0.f;
        }
    };

    float acc[2][4][4] = {};

    ld_tiles(kbeg);
    int buf = 0;
    for (int k0 = kbeg; k0 < kend; k0 += 16) {
        {
            float av[4] = {areg.x, areg.y, areg.z, areg.w};
            #pragma unroll
            for (int j = 0; j < 4; j++) {
                float v = av[j];
                if (RELU_A) v = fmaxf(v, 0.f);
                unsigned h, l; tf32split(v, h, l);
                AS(buf, 0, ac + j, ar) = __uint_as_float(h);
                AS(buf, 1, ac + j, ar) = __uint_as_float(l);
            }
            #pragma unroll
            for (int i = 0; i < 8; i++) {
                int idx = t + i * 256;
                int br = idx >> 7;
                int bc = idx & 127;
                unsigned h, l; tf32split(breg[i], h, l);
                BS(buf, 0, br, bc) = __uint_as_float(h);
                BS(buf, 1, br, bc) = __uint_as_float(l);
            }
        }
        __syncthreads();

        if (k0 + 16 < kend) ld_tiles(k0 + 16);

        #pragma unroll
        for (int kk = 0; kk < 16; kk += 8) {
            unsigned ah[2][4], al[2][4];
            #pragma unroll
            for (int mt = 0; mt < 2; mt++) {
                int row = wm + mt * 16 + g;
                ah[mt][0] = __float_as_uint(AS(buf, 0, kk + tq, row));
                al[mt][0] = __float_as_uint(AS(buf, 1, kk + tq, row));
                ah[mt][1] = __float_as_uint(AS(buf, 0, kk + tq, row + 8));
                al[mt][1] = __float_as_uint(AS(buf, 1, kk + tq, row + 8));
                ah[mt][2] = __float_as_uint(AS(buf, 0, kk + tq + 4, row));
                al[mt][2] = __float_as_uint(AS(buf, 1, kk + tq + 4, row));
                ah[mt][3] = __float_as_uint(AS(buf, 0, kk + tq + 4, row + 8));
                al[mt][3] = __float_as_uint(AS(buf, 1, kk + tq + 4, row + 8));
            }
            unsigned bh[4][2], bl[4][2];
            #pragma unroll
            for (int nt = 0; nt < 4; nt++) {
                int col = wn + nt * 8 + g;
                bh[nt][0] = __float_as_uint(BS(buf, 0, kk + tq, col));
                bl[nt][0] = __float_as_uint(BS(buf, 1, kk + tq, col));
                bh[nt][1] = __float_as_uint(BS(buf, 0, kk + tq + 4, col));
                bl[nt][1] = __float_as_uint(BS(buf, 1, kk + tq + 4, col));
            }
            #pragma unroll
            for (int mt = 0; mt < 2; mt++) {
                #pragma unroll
                for (int nt = 0; nt < 4; nt++) {
                    mma8(acc[mt][nt], ah[mt], bl[nt]);
                    mma8(acc[mt][nt], al[mt], bh[nt]);
                    mma8(acc[mt][nt], ah[mt], bh[nt]);
                }
            }
        }
        __syncthreads();
        buf ^= 1;
    }

    #pragma unroll
    for (int mt = 0; mt < 2; mt++) {
        int row = bm + wm + mt * 16 + g;
        #pragma unroll
        for (int nt = 0; nt < 4; nt++) {
            int col = bn + wn + nt * 8 + tq * 2;
            float* p0 = out + (long)row * ldc + col;
            float* p1 = out + (long)(row + 8) * ldc + col;
            if (col < N) {
                atomicAdd(p0, acc[mt][nt][0]);
                atomicAdd(p1, acc[mt][nt][2]);
            }
            if (col + 1 < N) {
                atomicAdd(p0 + 1, acc[mt][nt][1]);
                atomicAdd(p1 + 1, acc[mt][nt][3]);
            }
        }
    }
#undef AS
#undef BS
}

// ---------------------------------------------------------------------------

extern "C" void kernel_launch(void* const* d_in, const int* in_sizes, int n_in,
                              void* d_out, int out_size) {
    const float* node_feat = (const float*)d_in[0];
    const float* edge_feat = (const float*)d_in[1];
    const float* qemb      = (const float*)d_in[2];
    const int*   node_seg  = (const int*)d_in[3];
    const int*   edge_seg  = (const int*)d_in[4];
    const float* W_lang = (const float*)d_in[5];
    const float* b_lang = (const float*)d_in[6];
    const float* W_mid  = (const float*)d_in[7];
    const float* b_mid  = (const float*)d_in[8];
    const float* W_mid2 = (const float*)d_in[9];
    const float* b_mid2 = (const float*)d_in[10];
    const float* W_ans  = (const float*)d_in[11];
    const float* b_ans  = (const float*)d_in[12];

    const int N = in_sizes[3];
    const int E = in_sizes[4];
    const int A = in_sizes[12];   // 3129
    const int SMB = GEMM_SMEM_FLOATS * 4;

    float *pooled, *mid, *mid2;
    cudaGetSymbolAddress((void**)&pooled, g_pooled);
    cudaGetSymbolAddress((void**)&mid, g_mid);
    cudaGetSymbolAddress((void**)&mid2, g_mid2);

    static cudaStream_t s1 = nullptr, s2 = nullptr, s3 = nullptr;
    static cudaEvent_t evStart, evFork, evN, evE1, evMN, evML, evME1;
    if (!s1) {
        cudaStreamCreateWithFlags(&s1, cudaStreamNonBlocking);
        cudaStreamCreateWithFlags(&s2, cudaStreamNonBlocking);
        cudaStreamCreateWithFlags(&s3, cudaStreamNonBlocking);
        cudaEventCreateWithFlags(&evStart, cudaEventDisableTiming);
        cudaEventCreateWithFlags(&evFork, cudaEventDisableTiming);
        cudaEventCreateWithFlags(&evN, cudaEventDisableTiming);
        cudaEventCreateWithFlags(&evE1, cudaEventDisableTiming);
        cudaEventCreateWithFlags(&evMN, cudaEventDisableTiming);
        cudaEventCreateWithFlags(&evML, cudaEventDisableTiming);
        cudaEventCreateWithFlags(&evME1, cudaEventDisableTiming);
        cudaFuncSetAttribute(gemm_tf32_atomic<false>,
                             cudaFuncAttributeMaxDynamicSharedMemorySize, SMB);
        cudaFuncSetAttribute(gemm_tf32_atomic<true>,
                             cudaFuncAttributeMaxDynamicSharedMemorySize, SMB);
    }

    // Fork s1 FROM THE CAPTURE STREAM before any s1 work (capture-legal).
    cudaEventRecord(evStart, 0);
    cudaStreamWaitEvent(s1, evStart, 0);

    // s1: d_out bias init (off critical path, now properly captured)
    out_init_kernel<<<784, 256, 0, s1>>>(b_ans, (float*)d_out, A);

    // s0: pooled/mid/mid2 init
    init_kernel<<<512, 256>>>(b_lang, b_mid, b_mid2);
    cudaEventRecord(evFork, 0);

    // s1: lang chain (needs init; overlaps node seg-sum)
    cudaStreamWaitEvent(s1, evFork, 0);
    gemm_tf32_atomic<false><<<dim3(6, 4, 12), 256, SMB, s1>>>(
        qemb, HDIM, W_lang, HDIM, pooled + 2 * HDIM, C3H, NGRAPH, HDIM, 64);
    gemm_tf32_atomic<false><<<dim3(6, 4, 12), 256, SMB, s1>>>(
        pooled + 2 * HDIM, C3H, W_mid + 2 * HDIM * HDIM, HDIM,
        mid, HDIM, NGRAPH, HDIM, 64);
    cudaEventRecord(evML, s1);

    // s0: node seg-sum (full rows)
    seg_sum_full<<<(N + SEG_ROWS - 1) / SEG_ROWS, 192>>>(node_feat, node_seg, N, 0);
    cudaEventRecord(evN, 0);

    // s0: edge seg-sum, column halves
    seg_sum_half<<<(E + SEG_ROWS - 1) / SEG_ROWS, 192>>>(edge_feat, edge_seg, E, 0, HDIM);
    cudaEventRecord(evE1, 0);
    seg_sum_half<<<(E + SEG_ROWS - 1) / SEG_ROWS, 192>>>(edge_feat, edge_seg, E, 384, HDIM + 384);

    // s2: mid += nodes @ W_mid[0:768]   (overlaps edge seg-sums)
    cudaStreamWaitEvent(s2, evN, 0);
    gemm_tf32_atomic<false><<<dim3(6, 4, 12), 256, SMB, s2>>>(
        pooled, C3H, W_mid, HDIM, mid, HDIM, NGRAPH, HDIM, 64);
    cudaEventRecord(evMN, s2);

    // s3: mid += edges[:, :384] @ W_mid[768:1152]  (overlaps edge half 2)
    cudaStreamWaitEvent(s3, evE1, 0);
    gemm_tf32_atomic<false><<<dim3(6, 4, 6), 256, SMB, s3>>>(
        pooled + HDIM, C3H, W_mid + HDIM * HDIM, HDIM, mid, HDIM, NGRAPH, HDIM, 64);
    cudaEventRecord(evME1, s3);

    // s0: mid += edges[:, 384:768] @ W_mid[1152:1536]
    gemm_tf32_atomic<false><<<dim3(6, 4, 6), 256, SMB>>>(
        pooled + HDIM + 384, C3H, W_mid + (HDIM + 384) * (long)HDIM, HDIM,
        mid, HDIM, NGRAPH, HDIM, 64);

    // join; tail on s0
    cudaStreamWaitEvent(0, evMN, 0);
    cudaStreamWaitEvent(0, evML, 0);
    cudaStreamWaitEvent(0, evME1, 0);

    // mid2 += relu(mid) @ W_mid2
    gemm_tf32_atomic<true><<<dim3(6, 4, 12), 256, SMB>>>(
        mid, HDIM, W_mid2, HDIM, mid2, HDIM, NGRAPH, HDIM, 64);

    // d_out += relu(mid2) @ W_ans
    gemm_tf32_atomic<true><<<dim3(25, 4, 6), 256, SMB>>>(
        mid2, HDIM, W_ans, A, (float*)d_out, A, NGRAPH, A, 128);
}

// round 9
// speedup vs baseline: 1.4870x; 1.0003x over previous
#include <cuda_runtime.h>
#include <cstdint>

#define HDIM 768
#define NGRAPH 256
#define C3H (3 * HDIM)
#define SLOT (NGRAPH * HDIM)
#define ANS_PAD 3136                       // padded ldc for ans accumulator (even, 8B-aligned rows)

__device__ float g_pooled[NGRAPH * C3H];   // [B, 3H]: nodes | edges | lang
__device__ float g_mid[NGRAPH * HDIM];     // pre-relu mid accumulator (bias-init)
__device__ float g_mid2[NGRAPH * HDIM];    // pre-relu mid2 accumulator (bias-init)
__device__ float g_ans[NGRAPH * ANS_PAD];  // ans accumulator (zero-init, padded)

// pooled node/edge cols = 0, lang cols = b_lang; mid = b_mid; mid2 = b_mid2.
__global__ void init_kernel(const float* __restrict__ b_lang,
                            const float* __restrict__ b_mid,
                            const float* __restrict__ b_mid2) {
    const int n_pooled = NGRAPH * C3H;
    int total = n_pooled + 2 * SLOT;
    for (int i = blockIdx.x * blockDim.x + threadIdx.x; i < total;
         i += gridDim.x * blockDim.x) {
        if (i < n_pooled) {
            int c = i % C3H;
            g_pooled[i] = (c >= 2 * HDIM) ? __ldg(b_lang + c - 2 * HDIM) : 0.f;
        } else if (i < n_pooled + SLOT) {
            int j = i - n_pooled;
            g_mid[j] = __ldg(b_mid + (j % HDIM));
        } else {
            int j = i - n_pooled - SLOT;
            g_mid2[j] = __ldg(b_mid2 + (j % HDIM));
        }
    }
}

// g_ans = 0 (side stream, off critical path)
__global__ void ans_zero_kernel() {
    int total = NGRAPH * ANS_PAD / 4;
    float4 z = make_float4(0.f, 0.f, 0.f, 0.f);
    for (int i = blockIdx.x * blockDim.x + threadIdx.x; i < total;
         i += gridDim.x * blockDim.x)
        reinterpret_cast<float4*>(g_ans)[i] = z;
}

// d_out[m*A+n] = g_ans[m*ANS_PAD+n] + b_ans[n]
__global__ void ans_final_kernel(const float* __restrict__ b_ans,
                                 float* __restrict__ out, int A) {
    int total = NGRAPH * A;
    for (int i = blockIdx.x * blockDim.x + threadIdx.x; i < total;
         i += gridDim.x * blockDim.x) {
        int m = i / A, n = i - m * A;
        out[i] = g_ans[m * ANS_PAD + n] + __ldg(b_ans + n);
    }
}

// ---------------------------------------------------------------------------
// Segment sums (sorted ids). Register accumulation, atomic flush on change.
// ---------------------------------------------------------------------------
#define SEG_ROWS 256

__global__ void seg_sum_full(const float* __restrict__ feat,
                             const int* __restrict__ seg,
                             int n, int col_off) {
    const int tid = threadIdx.x;  // 0..191
    long r0 = (long)blockIdx.x * SEG_ROWS;
    long r1 = r0 + SEG_ROWS;
    if (r1 > n) r1 = n;
    if (r0 >= r1) return;

    const float* base = feat + tid * 4;
    float4 acc = make_float4(0.f, 0.f, 0.f, 0.f);
    int cur = __ldg(seg + r0);

    long r = r0;
    while (r + 8 <= r1) {
        int s7 = __ldg(seg + r + 7);
        float4 v[8];
        #pragma unroll
        for (int q = 0; q < 8; q++)
            v[q] = __ldcs(reinterpret_cast<const float4*>(base + (r + q) * HDIM));
        if (s7 == cur) {
            #pragma unroll
            for (int q = 0; q < 8; q++) {
                acc.x += v[q].x; acc.y += v[q].y;
                acc.z += v[q].z; acc.w += v[q].w;
            }
        } else {
            #pragma unroll
            for (int q = 0; q < 8; q++) {
                int s = __ldg(seg + r + q);
                if (s != cur) {
                    float* o = g_pooled + (long)cur * C3H + col_off + tid * 4;
                    atomicAdd(o + 0, acc.x); atomicAdd(o + 1, acc.y);
                    atomicAdd(o + 2, acc.z); atomicAdd(o + 3, acc.w);
                    acc = make_float4(0.f, 0.f, 0.f, 0.f);
                    cur = s;
                }
                acc.x += v[q].x; acc.y += v[q].y;
                acc.z += v[q].z; acc.w += v[q].w;
            }
        }
        r += 8;
    }
    for (; r < r1; ++r) {
        int s = __ldg(seg + r);
        if (s != cur) {
            float* o = g_pooled + (long)cur * C3H + col_off + tid * 4;
            atomicAdd(o + 0, acc.x); atomicAdd(o + 1, acc.y);
            atomicAdd(o + 2, acc.z); atomicAdd(o + 3, acc.w);
            acc = make_float4(0.f, 0.f, 0.f, 0.f);
            cur = s;
        }
        float4 v = __ldcs(reinterpret_cast<const float4*>(base + r * HDIM));
        acc.x += v.x; acc.y += v.y; acc.z += v.z; acc.w += v.w;
    }
    {
        float* o = g_pooled + (long)cur * C3H + col_off + tid * 4;
        atomicAdd(o + 0, acc.x); atomicAdd(o + 1, acc.y);
        atomicAdd(o + 2, acc.z); atomicAdd(o + 3, acc.w);
    }
}

// Half-row variant: cols [c0, c0+384), 192 thr x float2.
__global__ void seg_sum_half(const float* __restrict__ feat,
                             const int* __restrict__ seg,
                             int n, int c0, int col_off) {
    const int tid = threadIdx.x;  // 0..191
    long r0 = (long)blockIdx.x * SEG_ROWS;
    long r1 = r0 + SEG_ROWS;
    if (r1 > n) r1 = n;
    if (r0 >= r1) return;

    const float* base = feat + c0 + tid * 2;
    float2 acc = make_float2(0.f, 0.f);
    int cur = __ldg(seg + r0);

    long r = r0;
    while (r + 8 <= r1) {
        int s7 = __ldg(seg + r + 7);
        float2 v[8];
        #pragma unroll
        for (int q = 0; q < 8; q++)
            v[q] = __ldcs(reinterpret_cast<const float2*>(base + (r + q) * HDIM));
        if (s7 == cur) {
            #pragma unroll
            for (int q = 0; q < 8; q++) { acc.x += v[q].x; acc.y += v[q].y; }
        } else {
            #pragma unroll
            for (int q = 0; q < 8; q++) {
                int s = __ldg(seg + r + q);
                if (s != cur) {
                    float* o = g_pooled + (long)cur * C3H + col_off + tid * 2;
                    atomicAdd(o + 0, acc.x); atomicAdd(o + 1, acc.y);
                    acc = make_float2(0.f, 0.f);
                    cur = s;
                }
                acc.x += v[q].x; acc.y += v[q].y;
            }
        }
        r += 8;
    }
    for (; r < r1; ++r) {
        int s = __ldg(seg + r);
        if (s != cur) {
            float* o = g_pooled + (long)cur * C3H + col_off + tid * 2;
            atomicAdd(o + 0, acc.x); atomicAdd(o + 1, acc.y);
            acc = make_float2(0.f, 0.f);
            cur = s;
        }
        float2 v = __ldcs(reinterpret_cast<const float2*>(base + r * HDIM));
        acc.x += v.x; acc.y += v.y;
    }
    {
        float* o = g_pooled + (long)cur * C3H + col_off + tid * 2;
        atomicAdd(o + 0, acc.x); atomicAdd(o + 1, acc.y);
    }
}

// ---------------------------------------------------------------------------
// TF32 tensor-core GEMM, 3xTF32, split-K, vectorized red.global.add epilogue.
// Destination rows must be 8B aligned (ldc even). Optional relu on A at load.
// ---------------------------------------------------------------------------
#define GEMM_SMEM_FLOATS (2*2*16*72 + 2*2*16*136)   // 53248 B

__device__ __forceinline__ void tf32split(float x, unsigned& hi, unsigned& lo) {
    unsigned h;
    asm("cvt.rna.tf32.f32 %0, %1;" : "=r"(h) : "f"(x));
    float hf = __uint_as_float(h);
    unsigned l;
    float d = x - hf;
    asm("cvt.rna.tf32.f32 %0, %1;" : "=r"(l) : "f"(d));
    hi = h; lo = l;
}

__device__ __forceinline__ void mma8(float* d, const unsigned* a, const unsigned* b) {
    asm("mma.sync.aligned.m16n8k8.row.col.f32.tf32.tf32.f32 "
        "{%0,%1,%2,%3},{%4,%5,%6,%7},{%8,%9},{%0,%1,%2,%3};"
        : "+f"(d[0]), "+f"(d[1]), "+f"(d[2]), "+f"(d[3])
        : "r"(a[0]), "r"(a[1]), "r"(a[2]), "r"(a[3]), "r"(b[0]), "r"(b[1]));
}

__device__ __forceinline__ void red2(float* p, float a, float b) {
    asm volatile("red.global.add.v2.f32 [%0], {%1, %2};"
                 :: "l"(p), "f"(a), "f"(b) : "memory");
}
__device__ __forceinline__ void red1(float* p, float a) {
    asm volatile("red.global.add.f32 [%0], %1;" :: "l"(p), "f"(a) : "memory");
}

template <bool RELU_A>
__global__ __launch_bounds__(256) void gemm_tf32_atomic(
    const float* __restrict__ A, int lda,
    const float* __restrict__ W, int ldw,
    float* __restrict__ out, int ldc,
    int M, int N, int Ksplit) {
    extern __shared__ float dynsmem[];
    float* AsB = dynsmem;                        // [2][2][16][72]
    float* BsB = dynsmem + 2 * 2 * 16 * 72;      // [2][2][16][136]
#define AS(b,h,k,m) AsB[((((b)*2+(h))*16+(k))*72)+(m)]
#define BS(b,h,k,n) BsB[((((b)*2+(h))*16+(k))*136)+(n)]

    const int t = threadIdx.x;
    const int wid = t >> 5;
    const int lane = t & 31;
    const int wm = (wid & 1) * 32;
    const int wn = (wid >> 1) * 32;
    const int bm = blockIdx.y * 64;
    const int bn = blockIdx.x * 128;
    const int g = lane >> 2;
    const int tq = lane & 3;

    const int kbeg = blockIdx.z * Ksplit;
    const int kend = kbeg + Ksplit;

    const int ar = t & 63;
    const int ac = (t >> 6) * 4;

    float4 areg;
    float breg[8];

    auto ld_tiles = [&](int k0) {
        areg = *reinterpret_cast<const float4*>(A + (long)(bm + ar) * lda + k0 + ac);
        #pragma unroll
        for (int i = 0; i < 8; i++) {
            int idx = t + i * 256;
            int br = idx >> 7;
            int bc = idx & 127;
            int gn = bn + bc;
            breg[i] = (gn < N) ? __ldg(W + (long)(k0 + br) * ldw + gn) : 0.f;
        }
    };

    float acc[2][4][4] = {};

    ld_tiles(kbeg);
    int buf = 0;
    for (int k0 = kbeg; k0 < kend; k0 += 16) {
        {
            float av[4] = {areg.x, areg.y, areg.z, areg.w};
            #pragma unroll
            for (int j = 0; j < 4; j++) {
                float v = av[j];
                if (RELU_A) v = fmaxf(v, 0.f);
                unsigned h, l; tf32split(v, h, l);
                AS(buf, 0, ac + j, ar) = __uint_as_float(h);
                AS(buf, 1, ac + j, ar) = __uint_as_float(l);
            }
            #pragma unroll
            for (int i = 0; i < 8; i++) {
                int idx = t + i * 256;
                int br = idx >> 7;
                int bc = idx & 127;
                unsigned h, l; tf32split(breg[i], h, l);
                BS(buf, 0, br, bc) = __uint_as_float(h);
                BS(buf, 1, br, bc) = __uint_as_float(l);
            }
        }
        __syncthreads();

        if (k0 + 16 < kend) ld_tiles(k0 + 16);

        #pragma unroll
        for (int kk = 0; kk < 16; kk += 8) {
            unsigned ah[2][4], al[2][4];
            #pragma unroll
            for (int mt = 0; mt < 2; mt++) {
                int row = wm + mt * 16 + g;
                ah[mt][0] = __float_as_uint(AS(buf, 0, kk + tq, row));
                al[mt][0] = __float_as_uint(AS(buf, 1, kk + tq, row));
                ah[mt][1] = __float_as_uint(AS(buf, 0, kk + tq, row + 8));
                al[mt][1] = __float_as_uint(AS(buf, 1, kk + tq, row + 8));
                ah[mt][2] = __float_as_uint(AS(buf, 0, kk + tq + 4, row));
                al[mt][2] = __float_as_uint(AS(buf, 1, kk + tq + 4, row));
                ah[mt][3] = __float_as_uint(AS(buf, 0, kk + tq + 4, row + 8));
                al[mt][3] = __float_as_uint(AS(buf, 1, kk + tq + 4, row + 8));
            }
            unsigned bh[4][2], bl[4][2];
            #pragma unroll
            for (int nt = 0; nt < 4; nt++) {
                int col = wn + nt * 8 + g;
                bh[nt][0] = __float_as_uint(BS(buf, 0, kk + tq, col));
                bl[nt][0] = __float_as_uint(BS(buf, 1, kk + tq, col));
                bh[nt][1] = __float_as_uint(BS(buf, 0, kk + tq + 4, col));
                bl[nt][1] = __float_as_uint(BS(buf, 1, kk + tq + 4, col));
            }
            #pragma unroll
            for (int mt = 0; mt < 2; mt++) {
                #pragma unroll
                for (int nt = 0; nt < 4; nt++) {
                    mma8(acc[mt][nt], ah[mt], bl[nt]);
                    mma8(acc[mt][nt], al[mt], bh[nt]);
                    mma8(acc[mt][nt], ah[mt], bh[nt]);
                }
            }
        }
        __syncthreads();
        buf ^= 1;
    }

    // Vectorized reduction epilogue (ldc even -> 8B aligned)
    #pragma unroll
    for (int mt = 0; mt < 2; mt++) {
        int row = bm + wm + mt * 16 + g;
        #pragma unroll
        for (int nt = 0; nt < 4; nt++) {
            int col = bn + wn + nt * 8 + tq * 2;
            float* p0 = out + (long)row * ldc + col;
            float* p1 = out + (long)(row + 8) * ldc + col;
            if (col + 1 < N) {
                red2(p0, acc[mt][nt][0], acc[mt][nt][1]);
                red2(p1, acc[mt][nt][2], acc[mt][nt][3]);
            } else if (col < N) {
                red1(p0, acc[mt][nt][0]);
                red1(p1, acc[mt][nt][2]);
            }
        }
    }
#undef AS
#undef BS
}

// ---------------------------------------------------------------------------

extern "C" void kernel_launch(void* const* d_in, const int* in_sizes, int n_in,
                              void* d_out, int out_size) {
    const float* node_feat = (const float*)d_in[0];
    const float* edge_feat = (const float*)d_in[1];
    const float* qemb      = (const float*)d_in[2];
    const int*   node_seg  = (const int*)d_in[3];
    const int*   edge_seg  = (const int*)d_in[4];
    const float* W_lang = (const float*)d_in[5];
    const float* b_lang = (const float*)d_in[6];
    const float* W_mid  = (const float*)d_in[7];
    const float* b_mid  = (const float*)d_in[8];
    const float* W_mid2 = (const float*)d_in[9];
    const float* b_mid2 = (const float*)d_in[10];
    const float* W_ans  = (const float*)d_in[11];
    const float* b_ans  = (const float*)d_in[12];

    const int N = in_sizes[3];
    const int E = in_sizes[4];
    const int A = in_sizes[12];   // 3129
    const int SMB = GEMM_SMEM_FLOATS * 4;

    float *pooled, *mid, *mid2, *ans;
    cudaGetSymbolAddress((void**)&pooled, g_pooled);
    cudaGetSymbolAddress((void**)&mid, g_mid);
    cudaGetSymbolAddress((void**)&mid2, g_mid2);
    cudaGetSymbolAddress((void**)&ans, g_ans);

    static cudaStream_t s1 = nullptr, s2 = nullptr, s3 = nullptr;
    static cudaEvent_t evStart, evFork, evN, evE1, evMN, evML, evME1, evZ;
    if (!s1) {
        cudaStreamCreateWithFlags(&s1, cudaStreamNonBlocking);
        cudaStreamCreateWithFlags(&s2, cudaStreamNonBlocking);
        cudaStreamCreateWithFlags(&s3, cudaStreamNonBlocking);
        cudaEventCreateWithFlags(&evStart, cudaEventDisableTiming);
        cudaEventCreateWithFlags(&evFork, cudaEventDisableTiming);
        cudaEventCreateWithFlags(&evN, cudaEventDisableTiming);
        cudaEventCreateWithFlags(&evE1, cudaEventDisableTiming);
        cudaEventCreateWithFlags(&evMN, cudaEventDisableTiming);
        cudaEventCreateWithFlags(&evML, cudaEventDisableTiming);
        cudaEventCreateWithFlags(&evME1, cudaEventDisableTiming);
        cudaEventCreateWithFlags(&evZ, cudaEventDisableTiming);
        cudaFuncSetAttribute(gemm_tf32_atomic<false>,
                             cudaFuncAttributeMaxDynamicSharedMemorySize, SMB);
        cudaFuncSetAttribute(gemm_tf32_atomic<true>,
                             cudaFuncAttributeMaxDynamicSharedMemorySize, SMB);
    }

    // Fork s1 from the capture stream before any s1 work (capture-legal).
    cudaEventRecord(evStart, 0);
    cudaStreamWaitEvent(s1, evStart, 0);

    // s1: zero the padded ans accumulator (off critical path)
    ans_zero_kernel<<<784, 256, 0, s1>>>();
    cudaEventRecord(evZ, s1);

    // s0: pooled/mid/mid2 init
    init_kernel<<<512, 256>>>(b_lang, b_mid, b_mid2);
    cudaEventRecord(evFork, 0);

    // s1: lang chain (needs init; overlaps node seg-sum)
    cudaStreamWaitEvent(s1, evFork, 0);
    gemm_tf32_atomic<false><<<dim3(6, 4, 12), 256, SMB, s1>>>(
        qemb, HDIM, W_lang, HDIM, pooled + 2 * HDIM, C3H, NGRAPH, HDIM, 64);
    gemm_tf32_atomic<false><<<dim3(6, 4, 12), 256, SMB, s1>>>(
        pooled + 2 * HDIM, C3H, W_mid + 2 * HDIM * HDIM, HDIM,
        mid, HDIM, NGRAPH, HDIM, 64);
    cudaEventRecord(evML, s1);

    // s0: node seg-sum (full rows)
    seg_sum_full<<<(N + SEG_ROWS - 1) / SEG_ROWS, 192>>>(node_feat, node_seg, N, 0);
    cudaEventRecord(evN, 0);

    // s0: edge seg-sum, column halves
    seg_sum_half<<<(E + SEG_ROWS - 1) / SEG_ROWS, 192>>>(edge_feat, edge_seg, E, 0, HDIM);
    cudaEventRecord(evE1, 0);
    seg_sum_half<<<(E + SEG_ROWS - 1) / SEG_ROWS, 192>>>(edge_feat, edge_seg, E, 384, HDIM + 384);

    // s2: mid += nodes @ W_mid[0:768]   (overlaps edge seg-sums)
    cudaStreamWaitEvent(s2, evN, 0);
    gemm_tf32_atomic<false><<<dim3(6, 4, 12), 256, SMB, s2>>>(
        pooled, C3H, W_mid, HDIM, mid, HDIM, NGRAPH, HDIM, 64);
    cudaEventRecord(evMN, s2);

    // s3: mid += edges[:, :384] @ W_mid[768:1152]  (overlaps edge half 2)
    cudaStreamWaitEvent(s3, evE1, 0);
    gemm_tf32_atomic<false><<<dim3(6, 4, 6), 256, SMB, s3>>>(
        pooled + HDIM, C3H, W_mid + HDIM * HDIM, HDIM, mid, HDIM, NGRAPH, HDIM, 64);
    cudaEventRecord(evME1, s3);

    // s0: mid += edges[:, 384:768] @ W_mid[1152:1536]
    gemm_tf32_atomic<false><<<dim3(6, 4, 6), 256, SMB>>>(
        pooled + HDIM + 384, C3H, W_mid + (HDIM + 384) * (long)HDIM, HDIM,
        mid, HDIM, NGRAPH, HDIM, 64);

    // join; tail on s0
    cudaStreamWaitEvent(0, evMN, 0);
    cudaStreamWaitEvent(0, evML, 0);
    cudaStreamWaitEvent(0, evME1, 0);

    // mid2 += relu(mid) @ W_mid2
    gemm_tf32_atomic<true><<<dim3(6, 4, 12), 256, SMB>>>(
        mid, HDIM, W_mid2, HDIM, mid2, HDIM, NGRAPH, HDIM, 64);

    // g_ans += relu(mid2) @ W_ans   (padded ldc, v2-aligned)
    cudaStreamWaitEvent(0, evZ, 0);
    gemm_tf32_atomic<true><<<dim3(25, 4, 6), 256, SMB>>>(
        mid2, HDIM, W_ans, A, ans, ANS_PAD, NGRAPH, A, 128);

    // d_out = g_ans + b_ans
    ans_final_kernel<<<784, 256>>>(b_ans, (float*)d_out, A);
}

// round 10
// speedup vs baseline: 1.4873x; 1.0002x over previous
#include <cuda_runtime.h>
#include <cstdint>

#define HDIM 768
#define NGRAPH 256
#define C3H (3 * HDIM)
#define SLOT (NGRAPH * HDIM)

__device__ float g_pooled[NGRAPH * C3H];   // [B, 3H]: nodes | edges | lang
__device__ float g_mid[NGRAPH * HDIM];     // pre-relu mid accumulator (bias-init)
__device__ float g_mid2[NGRAPH * HDIM];    // pre-relu mid2 accumulator (bias-init)

// pooled: node/edge cols = 0, lang cols = b_lang  (critical path, small)
__global__ void pooled_init_kernel(const float* __restrict__ b_lang) {
    int total = NGRAPH * C3H;
    for (int i = blockIdx.x * blockDim.x + threadIdx.x; i < total;
         i += gridDim.x * blockDim.x) {
        int c = i % C3H;
        g_pooled[i] = (c >= 2 * HDIM) ? __ldg(b_lang + c - 2 * HDIM) : 0.f;
    }
}

// mid=b_mid, mid2=b_mid2, d_out=b_ans  (side stream)
__global__ void rest_init_kernel(const float* __restrict__ b_mid,
                                 const float* __restrict__ b_mid2,
                                 const float* __restrict__ b_ans,
                                 float* __restrict__ out, int A) {
    int total = 2 * SLOT + NGRAPH * A;
    for (int i = blockIdx.x * blockDim.x + threadIdx.x; i < total;
         i += gridDim.x * blockDim.x) {
        if (i < SLOT) g_mid[i] = __ldg(b_mid + (i % HDIM));
        else if (i < 2 * SLOT) g_mid2[i - SLOT] = __ldg(b_mid2 + ((i - SLOT) % HDIM));
        else { int j = i - 2 * SLOT; out[j] = __ldg(b_ans + (j % A)); }
    }
}

// ---------------------------------------------------------------------------
// Segment sums (sorted ids). Register accumulation, atomic flush on change.
// ---------------------------------------------------------------------------
#define SEG_ROWS 256

__global__ void seg_sum_full(const float* __restrict__ feat,
                             const int* __restrict__ seg,
                             int n, int col_off) {
    const int tid = threadIdx.x;  // 0..191
    long r0 = (long)blockIdx.x * SEG_ROWS;
    long r1 = r0 + SEG_ROWS;
    if (r1 > n) r1 = n;
    if (r0 >= r1) return;

    const float* base = feat + tid * 4;
    float4 acc = make_float4(0.f, 0.f, 0.f, 0.f);
    int cur = __ldg(seg + r0);

    long r = r0;
    while (r + 8 <= r1) {
        int s7 = __ldg(seg + r + 7);
        float4 v[8];
        #pragma unroll
        for (int q = 0; q < 8; q++)
            v[q] = __ldcs(reinterpret_cast<const float4*>(base + (r + q) * HDIM));
        if (s7 == cur) {
            #pragma unroll
            for (int q = 0; q < 8; q++) {
                acc.x += v[q].x; acc.y += v[q].y;
                acc.z += v[q].z; acc.w += v[q].w;
            }
        } else {
            #pragma unroll
            for (int q = 0; q < 8; q++) {
                int s = __ldg(seg + r + q);
                if (s != cur) {
                    float* o = g_pooled + (long)cur * C3H + col_off + tid * 4;
                    atomicAdd(o + 0, acc.x); atomicAdd(o + 1, acc.y);
                    atomicAdd(o + 2, acc.z); atomicAdd(o + 3, acc.w);
                    acc = make_float4(0.f, 0.f, 0.f, 0.f);
                    cur = s;
                }
                acc.x += v[q].x; acc.y += v[q].y;
                acc.z += v[q].z; acc.w += v[q].w;
            }
        }
        r += 8;
    }
    for (; r < r1; ++r) {
        int s = __ldg(seg + r);
        if (s != cur) {
            float* o = g_pooled + (long)cur * C3H + col_off + tid * 4;
            atomicAdd(o + 0, acc.x); atomicAdd(o + 1, acc.y);
            atomicAdd(o + 2, acc.z); atomicAdd(o + 3, acc.w);
            acc = make_float4(0.f, 0.f, 0.f, 0.f);
            cur = s;
        }
        float4 v = __ldcs(reinterpret_cast<const float4*>(base + r * HDIM));
        acc.x += v.x; acc.y += v.y; acc.z += v.z; acc.w += v.w;
    }
    {
        float* o = g_pooled + (long)cur * C3H + col_off + tid * 4;
        atomicAdd(o + 0, acc.x); atomicAdd(o + 1, acc.y);
        atomicAdd(o + 2, acc.z); atomicAdd(o + 3, acc.w);
    }
}

// Half-row variant: cols [c0, c0+384), 192 thr x float2.
__global__ void seg_sum_half(const float* __restrict__ feat,
                             const int* __restrict__ seg,
                             int n, int c0, int col_off) {
    const int tid = threadIdx.x;  // 0..191
    long r0 = (long)blockIdx.x * SEG_ROWS;
    long r1 = r0 + SEG_ROWS;
    if (r1 > n) r1 = n;
    if (r0 >= r1) return;

    const float* base = feat + c0 + tid * 2;
    float2 acc = make_float2(0.f, 0.f);
    int cur = __ldg(seg + r0);

    long r = r0;
    while (r + 8 <= r1) {
        int s7 = __ldg(seg + r + 7);
        float2 v[8];
        #pragma unroll
        for (int q = 0; q < 8; q++)
            v[q] = __ldcs(reinterpret_cast<const float2*>(base + (r + q) * HDIM));
        if (s7 == cur) {
            #pragma unroll
            for (int q = 0; q < 8; q++) { acc.x += v[q].x; acc.y += v[q].y; }
        } else {
            #pragma unroll
            for (int q = 0; q < 8; q++) {
                int s = __ldg(seg + r + q);
                if (s != cur) {
                    float* o = g_pooled + (long)cur * C3H + col_off + tid * 2;
                    atomicAdd(o + 0, acc.x); atomicAdd(o + 1, acc.y);
                    acc = make_float2(0.f, 0.f);
                    cur = s;
                }
                acc.x += v[q].x; acc.y += v[q].y;
            }
        }
        r += 8;
    }
    for (; r < r1; ++r) {
        int s = __ldg(seg + r);
        if (s != cur) {
            float* o = g_pooled + (long)cur * C3H + col_off + tid * 2;
            atomicAdd(o + 0, acc.x); atomicAdd(o + 1, acc.y);
            acc = make_float2(0.f, 0.f);
            cur = s;
        }
        float2 v = __ldcs(reinterpret_cast<const float2*>(base + r * HDIM));
        acc.x += v.x; acc.y += v.y;
    }
    {
        float* o = g_pooled + (long)cur * C3H + col_off + tid * 2;
        atomicAdd(o + 0, acc.x); atomicAdd(o + 1, acc.y);
    }
}

// ---------------------------------------------------------------------------
// TF32 tensor-core GEMM, 3xTF32, split-K, 3-stage cp.async pipeline,
// red.global epilogue into bias-initialized destination.
// BM=64, BN=128, BK=16; 256 thr = 8 warps (2M x 4N), warp tile 32x32.
// Smem (raw f32, split at fragment read):
//   As[64][20] : bank (20g+tq)%32 all-distinct;  Bs[16][136] : (8tq+g) distinct.
// ---------------------------------------------------------------------------
#define STAGES 3
#define AS_STRIDE 20
#define BS_STRIDE 136
#define AS_SZ (64 * AS_STRIDE)
#define BS_SZ (16 * BS_STRIDE)
#define STAGE_SZ (AS_SZ + BS_SZ)
#define GEMM_SMEM_BYTES (STAGES * STAGE_SZ * 4)   // 41472 B (< 48KB default)

__device__ __forceinline__ void cp16(float* dst, const float* src) {
    unsigned d = (unsigned)__cvta_generic_to_shared(dst);
    asm volatile("cp.async.cg.shared.global [%0], [%1], 16;" :: "r"(d), "l"(src));
}
__device__ __forceinline__ void cp4(float* dst, const float* src) {
    unsigned d = (unsigned)__cvta_generic_to_shared(dst);
    asm volatile("cp.async.ca.shared.global [%0], [%1], 4;" :: "r"(d), "l"(src));
}
#define CP_COMMIT() asm volatile("cp.async.commit_group;" ::: "memory")
#define CP_WAIT2()  asm volatile("cp.async.wait_group 2;" ::: "memory")

__device__ __forceinline__ void tf32split(float x, unsigned& hi, unsigned& lo) {
    unsigned h;
    asm("cvt.rna.tf32.f32 %0, %1;" : "=r"(h) : "f"(x));
    float hf = __uint_as_float(h);
    unsigned l;
    float d = x - hf;
    asm("cvt.rna.tf32.f32 %0, %1;" : "=r"(l) : "f"(d));
    hi = h; lo = l;
}

__device__ __forceinline__ void mma8(float* d, const unsigned* a, const unsigned* b) {
    asm("mma.sync.aligned.m16n8k8.row.col.f32.tf32.tf32.f32 "
        "{%0,%1,%2,%3},{%4,%5,%6,%7},{%8,%9},{%0,%1,%2,%3};"
        : "+f"(d[0]), "+f"(d[1]), "+f"(d[2]), "+f"(d[3])
        : "r"(a[0]), "r"(a[1]), "r"(a[2]), "r"(a[3]), "r"(b[0]), "r"(b[1]));
}

__device__ __forceinline__ void red2(float* p, float a, float b) {
    asm volatile("red.global.add.v2.f32 [%0], {%1, %2};"
                 :: "l"(p), "f"(a), "f"(b) : "memory");
}
__device__ __forceinline__ void red1(float* p, float a) {
    asm volatile("red.global.add.f32 [%0], %1;" :: "l"(p), "f"(a) : "memory");
}

// RELU_A: relu on A at fragment read. BVEC: B rows 16B-aligned + full N tiles.
// CVEC: ldc even (v2 epilogue). Internal GEMMs: <*,true,true>; ans: <true,false,false>.
template <bool RELU_A, bool BVEC, bool CVEC>
__global__ __launch_bounds__(256) void gemm_cp(
    const float* __restrict__ A, int lda,
    const float* __restrict__ W, int ldw,
    float* __restrict__ out, int ldc,
    int N, int Ksplit) {
    extern __shared__ float sm[];

    const int t = threadIdx.x;
    const int wid = t >> 5;
    const int lane = t & 31;
    const int wm = (wid & 1) * 32;
    const int wn = (wid >> 1) * 32;
    const int bm = blockIdx.y * 64;
    const int bn = blockIdx.x * 128;
    const int g = lane >> 2;
    const int tq = lane & 3;

    const int kbeg = blockIdx.z * Ksplit;
    const int ktiles = Ksplit / 16;

    const int ar = t & 63;      // A row
    const int aq = t >> 6;      // A 16B chunk (0..3)

#define AS(s,m,k) sm[(s)*STAGE_SZ + (m)*AS_STRIDE + (k)]
#define BS(s,k,n) sm[(s)*STAGE_SZ + AS_SZ + (k)*BS_STRIDE + (n)]

    auto issue = [&](int s, int tile) {
        int k0 = kbeg + tile * 16;
        cp16(&AS(s, ar, aq * 4), A + (long)(bm + ar) * lda + k0 + aq * 4);
        if (BVEC) {
            #pragma unroll
            for (int i = 0; i < 2; i++) {
                int idx = t + i * 256;
                int br = idx >> 5;
                int bc = (idx & 31) * 4;
                cp16(&BS(s, br, bc), W + (long)(k0 + br) * ldw + bn + bc);
            }
        } else {
            #pragma unroll
            for (int i = 0; i < 8; i++) {
                int idx = t + i * 256;
                int br = idx >> 7;
                int bc = idx & 127;
                int gn = bn + bc;
                if (gn < N) cp4(&BS(s, br, bc), W + (long)(k0 + br) * ldw + gn);
                else BS(s, br, bc) = 0.f;
            }
        }
    };

    float acc[2][4][4] = {};

    // prologue: stages 0,1 in flight
    issue(0, 0); CP_COMMIT();
    if (ktiles > 1) issue(1, 1);
    CP_COMMIT();

    for (int i = 0; i < ktiles; i++) {
        if (i + 2 < ktiles) issue((i + 2) % STAGES, i + 2);
        CP_COMMIT();               // always one group per iteration
        CP_WAIT2();                // tile i complete
        __syncthreads();

        const int s = i % STAGES;
        #pragma unroll
        for (int kk = 0; kk < 16; kk += 8) {
            unsigned ah[2][4], al[2][4];
            #pragma unroll
            for (int mt = 0; mt < 2; mt++) {
                int row = wm + mt * 16 + g;
                float x0 = AS(s, row,     kk + tq);
                float x1 = AS(s, row + 8, kk + tq);
                float x2 = AS(s, row,     kk + tq + 4);
                float x3 = AS(s, row + 8, kk + tq + 4);
                if (RELU_A) {
                    x0 = fmaxf(x0, 0.f); x1 = fmaxf(x1, 0.f);
                    x2 = fmaxf(x2, 0.f); x3 = fmaxf(x3, 0.f);
                }
                tf32split(x0, ah[mt][0], al[mt][0]);
                tf32split(x1, ah[mt][1], al[mt][1]);
                tf32split(x2, ah[mt][2], al[mt][2]);
                tf32split(x3, ah[mt][3], al[mt][3]);
            }
            unsigned bh[4][2], bl[4][2];
            #pragma unroll
            for (int nt = 0; nt < 4; nt++) {
                int col = wn + nt * 8 + g;
                tf32split(BS(s, kk + tq,     col), bh[nt][0], bl[nt][0]);
                tf32split(BS(s, kk + tq + 4, col), bh[nt][1], bl[nt][1]);
            }
            #pragma unroll
            for (int mt = 0; mt < 2; mt++) {
                #pragma unroll
                for (int nt = 0; nt < 4; nt++) {
                    mma8(acc[mt][nt], ah[mt], bl[nt]);   // hi*lo
                    mma8(acc[mt][nt], al[mt], bh[nt]);   // lo*hi
                    mma8(acc[mt][nt], ah[mt], bh[nt]);   // hi*hi
                }
            }
        }
        __syncthreads();           // all warps done reading stage before reuse
    }

    // reduction epilogue into bias-initialized destination
    #pragma unroll
    for (int mt = 0; mt < 2; mt++) {
        int row = bm + wm + mt * 16 + g;
        #pragma unroll
        for (int nt = 0; nt < 4; nt++) {
            int col = bn + wn + nt * 8 + tq * 2;
            float* p0 = out + (long)row * ldc + col;
            float* p1 = out + (long)(row + 8) * ldc + col;
            if (CVEC) {
                if (col + 1 < N) {
                    red2(p0, acc[mt][nt][0], acc[mt][nt][1]);
                    red2(p1, acc[mt][nt][2], acc[mt][nt][3]);
                } else if (col < N) {
                    red1(p0, acc[mt][nt][0]);
                    red1(p1, acc[mt][nt][2]);
                }
            } else {
                if (col < N)     { red1(p0, acc[mt][nt][0]); red1(p1, acc[mt][nt][2]); }
                if (col + 1 < N) { red1(p0 + 1, acc[mt][nt][1]); red1(p1 + 1, acc[mt][nt][3]); }
            }
        }
    }
#undef AS
#undef BS
}

// ---------------------------------------------------------------------------

extern "C" void kernel_launch(void* const* d_in, const int* in_sizes, int n_in,
                              void* d_out, int out_size) {
    const float* node_feat = (const float*)d_in[0];
    const float* edge_feat = (const float*)d_in[1];
    const float* qemb      = (const float*)d_in[2];
    const int*   node_seg  = (const int*)d_in[3];
    const int*   edge_seg  = (const int*)d_in[4];
    const float* W_lang = (const float*)d_in[5];
    const float* b_lang = (const float*)d_in[6];
    const float* W_mid  = (const float*)d_in[7];
    const float* b_mid  = (const float*)d_in[8];
    const float* W_mid2 = (const float*)d_in[9];
    const float* b_mid2 = (const float*)d_in[10];
    const float* W_ans  = (const float*)d_in[11];
    const float* b_ans  = (const float*)d_in[12];

    const int N = in_sizes[3];
    const int E = in_sizes[4];
    const int A = in_sizes[12];   // 3129

    float *pooled, *mid, *mid2;
    cudaGetSymbolAddress((void**)&pooled, g_pooled);
    cudaGetSymbolAddress((void**)&mid, g_mid);
    cudaGetSymbolAddress((void**)&mid2, g_mid2);

    static cudaStream_t s1 = nullptr, s2 = nullptr, s3 = nullptr;
    static cudaEvent_t evStart, evFork, evInit, evN, evE1, evMN, evML, evME1;
    if (!s1) {
        cudaStreamCreateWithFlags(&s1, cudaStreamNonBlocking);
        cudaStreamCreateWithFlags(&s2, cudaStreamNonBlocking);
        cudaStreamCreateWithFlags(&s3, cudaStreamNonBlocking);
        cudaEventCreateWithFlags(&evStart, cudaEventDisableTiming);
        cudaEventCreateWithFlags(&evFork, cudaEventDisableTiming);
        cudaEventCreateWithFlags(&evInit, cudaEventDisableTiming);
        cudaEventCreateWithFlags(&evN, cudaEventDisableTiming);
        cudaEventCreateWithFlags(&evE1, cudaEventDisableTiming);
        cudaEventCreateWithFlags(&evMN, cudaEventDisableTiming);
        cudaEventCreateWithFlags(&evML, cudaEventDisableTiming);
        cudaEventCreateWithFlags(&evME1, cudaEventDisableTiming);
    }

    // Fork s1 from the capture stream before any s1 work (capture-legal).
    cudaEventRecord(evStart, 0);
    cudaStreamWaitEvent(s1, evStart, 0);

    // s1: mid/mid2/d_out bias init (off critical path)
    rest_init_kernel<<<784, 256, 0, s1>>>(b_mid, b_mid2, b_ans, (float*)d_out, A);
    cudaEventRecord(evInit, s1);

    // s0: pooled init only (small; gates node seg-sum and lang GEMM)
    pooled_init_kernel<<<512, 256>>>(b_lang);
    cudaEventRecord(evFork, 0);

    // s1: lang chain (overlaps node seg-sum)
    cudaStreamWaitEvent(s1, evFork, 0);
    gemm_cp<false, true, true><<<dim3(6, 4, 12), 256, GEMM_SMEM_BYTES, s1>>>(
        qemb, HDIM, W_lang, HDIM, pooled + 2 * HDIM, C3H, HDIM, 64);
    gemm_cp<false, true, true><<<dim3(6, 4, 12), 256, GEMM_SMEM_BYTES, s1>>>(
        pooled + 2 * HDIM, C3H, W_mid + 2 * HDIM * HDIM, HDIM, mid, HDIM, HDIM, 64);
    cudaEventRecord(evML, s1);

    // s0: node seg-sum (full rows)
    seg_sum_full<<<(N + SEG_ROWS - 1) / SEG_ROWS, 192>>>(node_feat, node_seg, N, 0);
    cudaEventRecord(evN, 0);

    // s0: edge seg-sum, column halves
    seg_sum_half<<<(E + SEG_ROWS - 1) / SEG_ROWS, 192>>>(edge_feat, edge_seg, E, 0, HDIM);
    cudaEventRecord(evE1, 0);
    seg_sum_half<<<(E + SEG_ROWS - 1) / SEG_ROWS, 192>>>(edge_feat, edge_seg, E, 384, HDIM + 384);

    // s2: mid += nodes @ W_mid[0:768]   (overlaps edge seg-sums)
    cudaStreamWaitEvent(s2, evN, 0);
    cudaStreamWaitEvent(s2, evInit, 0);
    gemm_cp<false, true, true><<<dim3(6, 4, 12), 256, GEMM_SMEM_BYTES, s2>>>(
        pooled, C3H, W_mid, HDIM, mid, HDIM, HDIM, 64);
    cudaEventRecord(evMN, s2);

    // s3: mid += edges[:, :384] @ W_mid[768:1152]  (overlaps edge half 2)
    cudaStreamWaitEvent(s3, evE1, 0);
    cudaStreamWaitEvent(s3, evInit, 0);
    gemm_cp<false, true, true><<<dim3(6, 4, 6), 256, GEMM_SMEM_BYTES, s3>>>(
        pooled + HDIM, C3H, W_mid + HDIM * HDIM, HDIM, mid, HDIM, HDIM, 64);
    cudaEventRecord(evME1, s3);

    // s0: mid += edges[:, 384:768] @ W_mid[1152:1536]
    cudaStreamWaitEvent(0, evInit, 0);
    gemm_cp<false, true, true><<<dim3(6, 4, 6), 256, GEMM_SMEM_BYTES>>>(
        pooled + HDIM + 384, C3H, W_mid + (HDIM + 384) * (long)HDIM, HDIM,
        mid, HDIM, HDIM, 64);

    // join; tail on s0
    cudaStreamWaitEvent(0, evMN, 0);
    cudaStreamWaitEvent(0, evML, 0);
    cudaStreamWaitEvent(0, evME1, 0);

    // mid2 += relu(mid) @ W_mid2
    gemm_cp<true, true, true><<<dim3(6, 4, 12), 256, GEMM_SMEM_BYTES>>>(
        mid, HDIM, W_mid2, HDIM, mid2, HDIM, HDIM, 64);

    // d_out += relu(mid2) @ W_ans  (scalar red; d_out pre-initialized with b_ans)
    gemm_cp<true, false, false><<<dim3(25, 4, 6), 256, GEMM_SMEM_BYTES>>>(
        mid2, HDIM, W_ans, A, (float*)d_out, A, A, 128);
}

// round 11
// speedup vs baseline: 1.5248x; 1.0252x over previous
#include <cuda_runtime.h>
#include <cstdint>

#define HDIM 768
#define NGRAPH 256
#define C3H (3 * HDIM)
#define SLOT (NGRAPH * HDIM)

__device__ float g_pooled[NGRAPH * C3H];   // [B, 3H]: nodes | edges | lang
__device__ float g_mid[NGRAPH * HDIM];     // pre-relu mid accumulator (bias-init)
__device__ float g_mid2[NGRAPH * HDIM];    // pre-relu mid2 accumulator (bias-init)

// Critical path: zero ONLY node+edge cols of pooled (1.5 MB)
__global__ void pooled_zero_kernel() {
    int total = NGRAPH * 2 * HDIM;
    for (int i = blockIdx.x * blockDim.x + threadIdx.x; i < total;
         i += gridDim.x * blockDim.x) {
        int m = i / (2 * HDIM), c = i - m * (2 * HDIM);
        g_pooled[m * C3H + c] = 0.f;
    }
}

// Side stream: pooled lang cols = b_lang; mid=b_mid; mid2=b_mid2; d_out=b_ans
__global__ void rest_init_kernel(const float* __restrict__ b_lang,
                                 const float* __restrict__ b_mid,
                                 const float* __restrict__ b_mid2,
                                 const float* __restrict__ b_ans,
                                 float* __restrict__ out, int A) {
    int total = SLOT + 2 * SLOT + NGRAPH * A;
    for (int i = blockIdx.x * blockDim.x + threadIdx.x; i < total;
         i += gridDim.x * blockDim.x) {
        if (i < SLOT) {
            int m = i / HDIM, h = i - m * HDIM;
            g_pooled[m * C3H + 2 * HDIM + h] = __ldg(b_lang + h);
        } else if (i < 2 * SLOT) {
            int j = i - SLOT;
            g_mid[j] = __ldg(b_mid + (j % HDIM));
        } else if (i < 3 * SLOT) {
            int j = i - 2 * SLOT;
            g_mid2[j] = __ldg(b_mid2 + (j % HDIM));
        } else {
            int j = i - 3 * SLOT;
            out[j] = __ldg(b_ans + (j % A));
        }
    }
}

// ---------------------------------------------------------------------------
// Segment sums (sorted ids). Register accumulation, atomic flush on change.
// Unroll x16 (MLP=16) for latency hiding at DRAM.
// ---------------------------------------------------------------------------
#define SEG_ROWS 256

__global__ __launch_bounds__(192) void seg_sum_full(
    const float* __restrict__ feat, const int* __restrict__ seg,
    int n, int col_off) {
    const int tid = threadIdx.x;  // 0..191
    long r0 = (long)blockIdx.x * SEG_ROWS;
    long r1 = r0 + SEG_ROWS;
    if (r1 > n) r1 = n;
    if (r0 >= r1) return;

    const float* base = feat + tid * 4;
    float4 acc = make_float4(0.f, 0.f, 0.f, 0.f);
    int cur = __ldg(seg + r0);

    long r = r0;
    while (r + 16 <= r1) {
        int slast = __ldg(seg + r + 15);
        float4 v[16];
        #pragma unroll
        for (int q = 0; q < 16; q++)
            v[q] = __ldcs(reinterpret_cast<const float4*>(base + (r + q) * HDIM));
        if (slast == cur) {
            #pragma unroll
            for (int q = 0; q < 16; q++) {
                acc.x += v[q].x; acc.y += v[q].y;
                acc.z += v[q].z; acc.w += v[q].w;
            }
        } else {
            #pragma unroll
            for (int q = 0; q < 16; q++) {
                int s = __ldg(seg + r + q);
                if (s != cur) {
                    float* o = g_pooled + (long)cur * C3H + col_off + tid * 4;
                    atomicAdd(o + 0, acc.x); atomicAdd(o + 1, acc.y);
                    atomicAdd(o + 2, acc.z); atomicAdd(o + 3, acc.w);
                    acc = make_float4(0.f, 0.f, 0.f, 0.f);
                    cur = s;
                }
                acc.x += v[q].x; acc.y += v[q].y;
                acc.z += v[q].z; acc.w += v[q].w;
            }
        }
        r += 16;
    }
    for (; r < r1; ++r) {
        int s = __ldg(seg + r);
        if (s != cur) {
            float* o = g_pooled + (long)cur * C3H + col_off + tid * 4;
            atomicAdd(o + 0, acc.x); atomicAdd(o + 1, acc.y);
            atomicAdd(o + 2, acc.z); atomicAdd(o + 3, acc.w);
            acc = make_float4(0.f, 0.f, 0.f, 0.f);
            cur = s;
        }
        float4 v = __ldcs(reinterpret_cast<const float4*>(base + r * HDIM));
        acc.x += v.x; acc.y += v.y; acc.z += v.z; acc.w += v.w;
    }
    {
        float* o = g_pooled + (long)cur * C3H + col_off + tid * 4;
        atomicAdd(o + 0, acc.x); atomicAdd(o + 1, acc.y);
        atomicAdd(o + 2, acc.z); atomicAdd(o + 3, acc.w);
    }
}

// Half-row variant: cols [c0, c0+384), 192 thr x float2, unroll x16.
__global__ __launch_bounds__(192) void seg_sum_half(
    const float* __restrict__ feat, const int* __restrict__ seg,
    int n, int c0, int col_off) {
    const int tid = threadIdx.x;  // 0..191
    long r0 = (long)blockIdx.x * SEG_ROWS;
    long r1 = r0 + SEG_ROWS;
    if (r1 > n) r1 = n;
    if (r0 >= r1) return;

    const float* base = feat + c0 + tid * 2;
    float2 acc = make_float2(0.f, 0.f);
    int cur = __ldg(seg + r0);

    long r = r0;
    while (r + 16 <= r1) {
        int slast = __ldg(seg + r + 15);
        float2 v[16];
        #pragma unroll
        for (int q = 0; q < 16; q++)
            v[q] = __ldcs(reinterpret_cast<const float2*>(base + (r + q) * HDIM));
        if (slast == cur) {
            #pragma unroll
            for (int q = 0; q < 16; q++) { acc.x += v[q].x; acc.y += v[q].y; }
        } else {
            #pragma unroll
            for (int q = 0; q < 16; q++) {
                int s = __ldg(seg + r + q);
                if (s != cur) {
                    float* o = g_pooled + (long)cur * C3H + col_off + tid * 2;
                    atomicAdd(o + 0, acc.x); atomicAdd(o + 1, acc.y);
                    acc = make_float2(0.f, 0.f);
                    cur = s;
                }
                acc.x += v[q].x; acc.y += v[q].y;
            }
        }
        r += 16;
    }
    for (; r < r1; ++r) {
        int s = __ldg(seg + r);
        if (s != cur) {
            float* o = g_pooled + (long)cur * C3H + col_off + tid * 2;
            atomicAdd(o + 0, acc.x); atomicAdd(o + 1, acc.y);
            acc = make_float2(0.f, 0.f);
            cur = s;
        }
        float2 v = __ldcs(reinterpret_cast<const float2*>(base + r * HDIM));
        acc.x += v.x; acc.y += v.y;
    }
    {
        float* o = g_pooled + (long)cur * C3H + col_off + tid * 2;
        atomicAdd(o + 0, acc.x); atomicAdd(o + 1, acc.y);
    }
}

// ---------------------------------------------------------------------------
// TF32 tensor-core GEMM, 3xTF32, split-K, 3-stage cp.async pipeline,
// red.global epilogue into bias-initialized destination.
// ---------------------------------------------------------------------------
#define STAGES 3
#define AS_STRIDE 20
#define BS_STRIDE 136
#define AS_SZ (64 * AS_STRIDE)
#define BS_SZ (16 * BS_STRIDE)
#define STAGE_SZ (AS_SZ + BS_SZ)
#define GEMM_SMEM_BYTES (STAGES * STAGE_SZ * 4)   // 41472 B

__device__ __forceinline__ void cp16(float* dst, const float* src) {
    unsigned d = (unsigned)__cvta_generic_to_shared(dst);
    asm volatile("cp.async.cg.shared.global [%0], [%1], 16;" :: "r"(d), "l"(src));
}
__device__ __forceinline__ void cp4(float* dst, const float* src) {
    unsigned d = (unsigned)__cvta_generic_to_shared(dst);
    asm volatile("cp.async.ca.shared.global [%0], [%1], 4;" :: "r"(d), "l"(src));
}
#define CP_COMMIT() asm volatile("cp.async.commit_group;" ::: "memory")
#define CP_WAIT2()  asm volatile("cp.async.wait_group 2;" ::: "memory")

__device__ __forceinline__ void tf32split(float x, unsigned& hi, unsigned& lo) {
    unsigned h;
    asm("cvt.rna.tf32.f32 %0, %1;" : "=r"(h) : "f"(x));
    float hf = __uint_as_float(h);
    unsigned l;
    float d = x - hf;
    asm("cvt.rna.tf32.f32 %0, %1;" : "=r"(l) : "f"(d));
    hi = h; lo = l;
}

__device__ __forceinline__ void mma8(float* d, const unsigned* a, const unsigned* b) {
    asm("mma.sync.aligned.m16n8k8.row.col.f32.tf32.tf32.f32 "
        "{%0,%1,%2,%3},{%4,%5,%6,%7},{%8,%9},{%0,%1,%2,%3};"
        : "+f"(d[0]), "+f"(d[1]), "+f"(d[2]), "+f"(d[3])
        : "r"(a[0]), "r"(a[1]), "r"(a[2]), "r"(a[3]), "r"(b[0]), "r"(b[1]));
}

__device__ __forceinline__ void red2(float* p, float a, float b) {
    asm volatile("red.global.add.v2.f32 [%0], {%1, %2};"
                 :: "l"(p), "f"(a), "f"(b) : "memory");
}
__device__ __forceinline__ void red1(float* p, float a) {
    asm volatile("red.global.add.f32 [%0], %1;" :: "l"(p), "f"(a) : "memory");
}

template <bool RELU_A, bool BVEC, bool CVEC>
__global__ __launch_bounds__(256) void gemm_cp(
    const float* __restrict__ A, int lda,
    const float* __restrict__ W, int ldw,
    float* __restrict__ out, int ldc,
    int N, int Ksplit) {
    extern __shared__ float sm[];

    const int t = threadIdx.x;
    const int wid = t >> 5;
    const int lane = t & 31;
    const int wm = (wid & 1) * 32;
    const int wn = (wid >> 1) * 32;
    const int bm = blockIdx.y * 64;
    const int bn = blockIdx.x * 128;
    const int g = lane >> 2;
    const int tq = lane & 3;

    const int kbeg = blockIdx.z * Ksplit;
    const int ktiles = Ksplit / 16;

    const int ar = t & 63;
    const int aq = t >> 6;

#define AS(s,m,k) sm[(s)*STAGE_SZ + (m)*AS_STRIDE + (k)]
#define BS(s,k,n) sm[(s)*STAGE_SZ + AS_SZ + (k)*BS_STRIDE + (n)]

    auto issue = [&](int s, int tile) {
        int k0 = kbeg + tile * 16;
        cp16(&AS(s, ar, aq * 4), A + (long)(bm + ar) * lda + k0 + aq * 4);
        if (BVEC) {
            #pragma unroll
            for (int i = 0; i < 2; i++) {
                int idx = t + i * 256;
                int br = idx >> 5;
                int bc = (idx & 31) * 4;
                cp16(&BS(s, br, bc), W + (long)(k0 + br) * ldw + bn + bc);
            }
        } else {
            #pragma unroll
            for (int i = 0; i < 8; i++) {
                int idx = t + i * 256;
                int br = idx >> 7;
                int bc = idx & 127;
                int gn = bn + bc;
                if (gn < N) cp4(&BS(s, br, bc), W + (long)(k0 + br) * ldw + gn);
                else BS(s, br, bc) = 0.f;
            }
        }
    };

    float acc[2][4][4] = {};

    issue(0, 0); CP_COMMIT();
    if (ktiles > 1) issue(1, 1);
    CP_COMMIT();

    for (int i = 0; i < ktiles; i++) {
        if (i + 2 < ktiles) issue((i + 2) % STAGES, i + 2);
        CP_COMMIT();
        CP_WAIT2();
        __syncthreads();

        const int s = i % STAGES;
        #pragma unroll
        for (int kk = 0; kk < 16; kk += 8) {
            unsigned ah[2][4], al[2][4];
            #pragma unroll
            for (int mt = 0; mt < 2; mt++) {
                int row = wm + mt * 16 + g;
                float x0 = AS(s, row,     kk + tq);
                float x1 = AS(s, row + 8, kk + tq);
                float x2 = AS(s, row,     kk + tq + 4);
                float x3 = AS(s, row + 8, kk + tq + 4);
                if (RELU_A) {
                    x0 = fmaxf(x0, 0.f); x1 = fmaxf(x1, 0.f);
                    x2 = fmaxf(x2, 0.f); x3 = fmaxf(x3, 0.f);
                }
                tf32split(x0, ah[mt][0], al[mt][0]);
                tf32split(x1, ah[mt][1], al[mt][1]);
                tf32split(x2, ah[mt][2], al[mt][2]);
                tf32split(x3, ah[mt][3], al[mt][3]);
            }
            unsigned bh[4][2], bl[4][2];
            #pragma unroll
            for (int nt = 0; nt < 4; nt++) {
                int col = wn + nt * 8 + g;
                tf32split(BS(s, kk + tq,     col), bh[nt][0], bl[nt][0]);
                tf32split(BS(s, kk + tq + 4, col), bh[nt][1], bl[nt][1]);
            }
            #pragma unroll
            for (int mt = 0; mt < 2; mt++) {
                #pragma unroll
                for (int nt = 0; nt < 4; nt++) {
                    mma8(acc[mt][nt], ah[mt], bl[nt]);
                    mma8(acc[mt][nt], al[mt], bh[nt]);
                    mma8(acc[mt][nt], ah[mt], bh[nt]);
                }
            }
        }
        __syncthreads();
    }

    #pragma unroll
    for (int mt = 0; mt < 2; mt++) {
        int row = bm + wm + mt * 16 + g;
        #pragma unroll
        for (int nt = 0; nt < 4; nt++) {
            int col = bn + wn + nt * 8 + tq * 2;
            float* p0 = out + (long)row * ldc + col;
            float* p1 = out + (long)(row + 8) * ldc + col;
            if (CVEC) {
                if (col + 1 < N) {
                    red2(p0, acc[mt][nt][0], acc[mt][nt][1]);
                    red2(p1, acc[mt][nt][2], acc[mt][nt][3]);
                } else if (col < N) {
                    red1(p0, acc[mt][nt][0]);
                    red1(p1, acc[mt][nt][2]);
                }
            } else {
                if (col < N)     { red1(p0, acc[mt][nt][0]); red1(p1, acc[mt][nt][2]); }
                if (col + 1 < N) { red1(p0 + 1, acc[mt][nt][1]); red1(p1 + 1, acc[mt][nt][3]); }
            }
        }
    }
#undef AS
#undef BS
}

// ---------------------------------------------------------------------------

extern "C" void kernel_launch(void* const* d_in, const int* in_sizes, int n_in,
                              void* d_out, int out_size) {
    const float* node_feat = (const float*)d_in[0];
    const float* edge_feat = (const float*)d_in[1];
    const float* qemb      = (const float*)d_in[2];
    const int*   node_seg  = (const int*)d_in[3];
    const int*   edge_seg  = (const int*)d_in[4];
    const float* W_lang = (const float*)d_in[5];
    const float* b_lang = (const float*)d_in[6];
    const float* W_mid  = (const float*)d_in[7];
    const float* b_mid  = (const float*)d_in[8];
    const float* W_mid2 = (const float*)d_in[9];
    const float* b_mid2 = (const float*)d_in[10];
    const float* W_ans  = (const float*)d_in[11];
    const float* b_ans  = (const float*)d_in[12];

    const int N = in_sizes[3];
    const int E = in_sizes[4];
    const int A = in_sizes[12];   // 3129

    float *pooled, *mid, *mid2;
    cudaGetSymbolAddress((void**)&pooled, g_pooled);
    cudaGetSymbolAddress((void**)&mid, g_mid);
    cudaGetSymbolAddress((void**)&mid2, g_mid2);

    static cudaStream_t s1 = nullptr, s2 = nullptr, s3 = nullptr;
    static cudaEvent_t evStart, evFork, evInit, evN, evE1, evMN, evML, evME1;
    if (!s1) {
        cudaStreamCreateWithFlags(&s1, cudaStreamNonBlocking);
        cudaStreamCreateWithFlags(&s2, cudaStreamNonBlocking);
        cudaStreamCreateWithFlags(&s3, cudaStreamNonBlocking);
        cudaEventCreateWithFlags(&evStart, cudaEventDisableTiming);
        cudaEventCreateWithFlags(&evFork, cudaEventDisableTiming);
        cudaEventCreateWithFlags(&evInit, cudaEventDisableTiming);
        cudaEventCreateWithFlags(&evN, cudaEventDisableTiming);
        cudaEventCreateWithFlags(&evE1, cudaEventDisableTiming);
        cudaEventCreateWithFlags(&evMN, cudaEventDisableTiming);
        cudaEventCreateWithFlags(&evML, cudaEventDisableTiming);
        cudaEventCreateWithFlags(&evME1, cudaEventDisableTiming);
    }

    // Fork s1 from the capture stream before any s1 work (capture-legal).
    cudaEventRecord(evStart, 0);
    cudaStreamWaitEvent(s1, evStart, 0);

    // s1: lang-bias + mid/mid2/d_out inits (off critical path)
    rest_init_kernel<<<784, 256, 0, s1>>>(b_lang, b_mid, b_mid2, b_ans,
                                          (float*)d_out, A);
    cudaEventRecord(evInit, s1);

    // s0: zero node/edge pooled cols only (small; gates node seg-sum)
    pooled_zero_kernel<<<384, 256>>>();
    cudaEventRecord(evFork, 0);

    // s1: lang chain (in-order after rest_init; overlaps node seg-sum)
    cudaStreamWaitEvent(s1, evFork, 0);
    gemm_cp<false, true, true><<<dim3(6, 4, 12), 256, GEMM_SMEM_BYTES, s1>>>(
        qemb, HDIM, W_lang, HDIM, pooled + 2 * HDIM, C3H, HDIM, 64);
    gemm_cp<false, true, true><<<dim3(6, 4, 12), 256, GEMM_SMEM_BYTES, s1>>>(
        pooled + 2 * HDIM, C3H, W_mid + 2 * HDIM * HDIM, HDIM, mid, HDIM, HDIM, 64);
    cudaEventRecord(evML, s1);

    // s0: node seg-sum (full rows)
    seg_sum_full<<<(N + SEG_ROWS - 1) / SEG_ROWS, 192>>>(node_feat, node_seg, N, 0);
    cudaEventRecord(evN, 0);

    // s0: edge seg-sum, column halves
    seg_sum_half<<<(E + SEG_ROWS - 1) / SEG_ROWS, 192>>>(edge_feat, edge_seg, E, 0, HDIM);
    cudaEventRecord(evE1, 0);
    seg_sum_half<<<(E + SEG_ROWS - 1) / SEG_ROWS, 192>>>(edge_feat, edge_seg, E, 384, HDIM + 384);

    // s2: mid += nodes @ W_mid[0:768]   (overlaps edge seg-sums)
    cudaStreamWaitEvent(s2, evN, 0);
    cudaStreamWaitEvent(s2, evInit, 0);
    gemm_cp<false, true, true><<<dim3(6, 4, 12), 256, GEMM_SMEM_BYTES, s2>>>(
        pooled, C3H, W_mid, HDIM, mid, HDIM, HDIM, 64);
    cudaEventRecord(evMN, s2);

    // s3: mid += edges[:, :384] @ W_mid[768:1152]  (overlaps edge half 2)
    cudaStreamWaitEvent(s3, evE1, 0);
    cudaStreamWaitEvent(s3, evInit, 0);
    gemm_cp<false, true, true><<<dim3(6, 4, 6), 256, GEMM_SMEM_BYTES, s3>>>(
        pooled + HDIM, C3H, W_mid + HDIM * HDIM, HDIM, mid, HDIM, HDIM, 64);
    cudaEventRecord(evME1, s3);

    // s0: mid += edges[:, 384:768] @ W_mid[1152:1536]
    cudaStreamWaitEvent(0, evInit, 0);
    gemm_cp<false, true, true><<<dim3(6, 4, 6), 256, GEMM_SMEM_BYTES>>>(
        pooled + HDIM + 384, C3H, W_mid + (HDIM + 384) * (long)HDIM, HDIM,
        mid, HDIM, HDIM, 64);

    // join; tail on s0
    cudaStreamWaitEvent(0, evMN, 0);
    cudaStreamWaitEvent(0, evML, 0);
    cudaStreamWaitEvent(0, evME1, 0);

    // mid2 += relu(mid) @ W_mid2
    gemm_cp<true, true, true><<<dim3(6, 4, 12), 256, GEMM_SMEM_BYTES>>>(
        mid, HDIM, W_mid2, HDIM, mid2, HDIM, HDIM, 64);

    // d_out += relu(mid2) @ W_ans  (splits 3: atomic elements halved vs 6)
    gemm_cp<true, false, false><<<dim3(25, 4, 3), 256, GEMM_SMEM_BYTES>>>(
        mid2, HDIM, W_ans, A, (float*)d_out, A, A, 256);
}